// round 15
// baseline (speedup 1.0000x reference)
#include <cuda_runtime.h>
#include <cuda_bf16.h>
#include <cstdint>
#include <cstddef>

// Problem constants
#define Bn   16
#define Ln   1024
#define DIMn 1024
#define NH   16
#define DK   64

#define OUT_ELEMS    (16*1024*1024)
#define ATTNS_ELEMS  (16*8*1024*1024)
#define ATTNF_ELEMS  (16*8*64*64)

// fp32 scratch (head-major Qh/Kh/Vh)
__device__ float g_qh[OUT_ELEMS];
__device__ float g_kh[OUT_ELEMS];
__device__ float g_vh[OUT_ELEMS];
// bf16 split scratch: 3 activation tensors + 4 weights
__device__ __nv_bfloat16 g_ahi3[3*OUT_ELEMS];
__device__ __nv_bfloat16 g_alo3[3*OUT_ELEMS];
__device__ __nv_bfloat16 g_whi4[4*DIMn*DIMn];
__device__ __nv_bfloat16 g_wlo4[4*DIMn*DIMn];
// bf16 head-major K/V echoed by the QKV GEMM epilogue
__device__ __nv_bfloat16 g_kbhi[OUT_ELEMS];
__device__ __nv_bfloat16 g_kblo[OUT_ELEMS];
__device__ __nv_bfloat16 g_vbhi[OUT_ELEMS];
__device__ __nv_bfloat16 g_vblo[OUT_ELEMS];

// ===========================================================================
// Common helpers
// ===========================================================================
#define CP_ASYNC16(dst, src) \
    asm volatile("cp.async.cg.shared.global [%0], [%1], 16;\n" :: "r"(dst), "l"(src))
#define CP_COMMIT() asm volatile("cp.async.commit_group;\n" ::: "memory")
#define CP_WAIT(n)  asm volatile("cp.async.wait_group %0;\n" :: "n"(n) : "memory")

#define LDSM_X4(r0, r1, r2, r3, addr) \
    asm volatile("ldmatrix.sync.aligned.m8n8.x4.shared.b16 {%0,%1,%2,%3}, [%4];" \
                 : "=r"(r0), "=r"(r1), "=r"(r2), "=r"(r3) : "r"(addr))
#define LDSM_X2_T(r0, r1, addr) \
    asm volatile("ldmatrix.sync.aligned.m8n8.x2.trans.shared.b16 {%0,%1}, [%2];" \
                 : "=r"(r0), "=r"(r1) : "r"(addr))

__device__ __forceinline__ void mma_bf16(float c[4], const uint32_t a[4], const uint32_t b[2]) {
    asm volatile(
        "mma.sync.aligned.m16n8k16.row.col.f32.bf16.bf16.f32 "
        "{%0,%1,%2,%3}, {%4,%5,%6,%7}, {%8,%9}, {%0,%1,%2,%3};\n"
        : "+f"(c[0]), "+f"(c[1]), "+f"(c[2]), "+f"(c[3])
        : "r"(a[0]), "r"(a[1]), "r"(a[2]), "r"(a[3]), "r"(b[0]), "r"(b[1]));
}

static __device__ __forceinline__ void split_pack(float x0, float x1,
                                                  uint32_t& hi, uint32_t& lo) {
    __nv_bfloat16 h0 = __float2bfloat16(x0);
    __nv_bfloat16 h1 = __float2bfloat16(x1);
    __nv_bfloat16 l0 = __float2bfloat16(x0 - __bfloat162float(h0));
    __nv_bfloat16 l1 = __float2bfloat16(x1 - __bfloat162float(h1));
    __nv_bfloat162 hp(h0, h1), lp(l0, l1);
    hi = *reinterpret_cast<uint32_t*>(&hp);
    lo = *reinterpret_cast<uint32_t*>(&lp);
}

// ===========================================================================
// Split kernels (fp32 -> bf16 hi/lo)
// ===========================================================================
__global__ __launch_bounds__(256) void split_a3_k(
    const float* __restrict__ X0, const float* __restrict__ X1,
    const float* __restrict__ X2,
    __nv_bfloat16* __restrict__ hi, __nv_bfloat16* __restrict__ lo)
{
    const int t = blockIdx.y;
    const float* X = (t == 0) ? X0 : (t == 1) ? X1 : X2;
    size_t obase = (size_t)t * OUT_ELEMS;
    int i = (blockIdx.x * 256 + threadIdx.x) * 4;
    float4 v = *(const float4*)(X + i);
    float x[4] = {v.x, v.y, v.z, v.w};
    __nv_bfloat16 h[4], l[4];
    #pragma unroll
    for (int j = 0; j < 4; j++) {
        h[j] = __float2bfloat16(x[j]);
        l[j] = __float2bfloat16(x[j] - __bfloat162float(h[j]));
    }
    __nv_bfloat162* hp = (__nv_bfloat162*)(hi + obase + i);
    __nv_bfloat162* lp = (__nv_bfloat162*)(lo + obase + i);
    hp[0] = __nv_bfloat162{h[0], h[1]}; hp[1] = __nv_bfloat162{h[2], h[3]};
    lp[0] = __nv_bfloat162{l[0], l[1]}; lp[1] = __nv_bfloat162{l[2], l[3]};
}

__global__ __launch_bounds__(256) void split_w4_k(
    const float* __restrict__ W0, const float* __restrict__ W1,
    const float* __restrict__ W2, const float* __restrict__ W3,
    __nv_bfloat16* __restrict__ hi, __nv_bfloat16* __restrict__ lo)
{
    __shared__ float t[32][33];
    const int wz = blockIdx.z;
    const float* W = (wz == 0) ? W0 : (wz == 1) ? W1 : (wz == 2) ? W2 : W3;
    size_t obase = (size_t)wz * DIMn * DIMn;
    const int tx = threadIdx.x, ty = threadIdx.y;
    const int n0 = blockIdx.x * 32, k0 = blockIdx.y * 32;
    #pragma unroll
    for (int j = 0; j < 32; j += 8)
        t[ty + j][tx] = W[(size_t)(k0 + ty + j) * DIMn + n0 + tx];
    __syncthreads();
    #pragma unroll
    for (int j = 0; j < 32; j += 8) {
        int n = n0 + ty + j, kk = k0 + tx;
        float x = t[tx][ty + j];
        __nv_bfloat16 h = __float2bfloat16(x);
        __nv_bfloat16 l = __float2bfloat16(x - __bfloat162float(h));
        hi[obase + (size_t)n * DIMn + kk] = h;
        lo[obase + (size_t)n * DIMn + kk] = l;
    }
}

// ===========================================================================
// Split-bf16 mma.sync GEMM mainloop (PASSING, unchanged).
// ===========================================================================
#define RS      40
#define TILB    (128*RS*2)
#define STAGEB  (4*TILB)
#define GSMEM   (2*STAGEB)

template<int MODE>
__device__ __forceinline__ void gemm_body(
    const __nv_bfloat16* __restrict__ Ahi, const __nv_bfloat16* __restrict__ Alo,
    const __nv_bfloat16* __restrict__ Bhi, const __nv_bfloat16* __restrict__ Blo,
    float* __restrict__ C, __nv_bfloat16* __restrict__ Ehi,
    __nv_bfloat16* __restrict__ Elo, char* smem)
{
    uint32_t sb;
    asm("{ .reg .u64 u; cvta.to.shared.u64 u, %1; cvt.u32.u64 %0, u; }" : "=r"(sb) : "l"(smem));

    const int tid  = threadIdx.x;
    const int lane = tid & 31;
    const int warp = tid >> 5;
    const int wm   = warp >> 2;
    const int wn   = warp & 3;
    const int g    = lane >> 2;
    const int t4   = lane & 3;

    const int row0 = blockIdx.y * 128;
    const int col0 = blockIdx.x * 128;

    const int sub = lane >> 3, r8 = lane & 7;
    const uint32_t loffA = (uint32_t)((r8 + (sub & 1) * 8) * 80 + (sub >> 1) * 16);
    const uint32_t loffB = (uint32_t)((r8 + (sub >> 1) * 8) * 80 + (sub & 1) * 16);

    const int ra = tid >> 2, ca = tid & 3;
    const int rb = (tid + 256) >> 2, cb = ca;

    auto prefetch = [&](int c, int st) {
        const int kc = c * 32;
        uint32_t s0 = sb + (uint32_t)st * STAGEB;
        {
            uint32_t d = s0 + (uint32_t)(ra * 80 + ca * 16);
            size_t ga = ((size_t)(row0 + ra) * 1024 + kc + ca * 8) * 2;
            size_t gb = ((size_t)(col0 + ra) * 1024 + kc + ca * 8) * 2;
            CP_ASYNC16(d,            (const char*)Ahi + ga);
            CP_ASYNC16(d + TILB,     (const char*)Alo + ga);
            CP_ASYNC16(d + 2*TILB,   (const char*)Bhi + gb);
            CP_ASYNC16(d + 3*TILB,   (const char*)Blo + gb);
        }
        {
            uint32_t d = s0 + (uint32_t)(rb * 80 + cb * 16);
            size_t ga = ((size_t)(row0 + rb) * 1024 + kc + cb * 8) * 2;
            size_t gb = ((size_t)(col0 + rb) * 1024 + kc + cb * 8) * 2;
            CP_ASYNC16(d,            (const char*)Ahi + ga);
            CP_ASYNC16(d + TILB,     (const char*)Alo + ga);
            CP_ASYNC16(d + 2*TILB,   (const char*)Bhi + gb);
            CP_ASYNC16(d + 3*TILB,   (const char*)Blo + gb);
        }
    };

    float acc[4][4][4];
    #pragma unroll
    for (int mt = 0; mt < 4; mt++)
        #pragma unroll
        for (int nt = 0; nt < 4; nt++)
            #pragma unroll
            for (int i = 0; i < 4; i++) acc[mt][nt][i] = 0.f;

    prefetch(0, 0); CP_COMMIT();
    prefetch(1, 1); CP_COMMIT();

    const int nk = 32;
    for (int c = 0; c < nk; c++) {
        const int st = c & 1;
        if (c + 1 < nk) { CP_WAIT(1); } else { CP_WAIT(0); }
        __syncthreads();

        const uint32_t s0 = sb + (uint32_t)st * STAGEB;
        const uint32_t aB = s0 + (uint32_t)(wm * 64) * 80;
        const uint32_t bB = s0 + 2 * TILB + (uint32_t)(wn * 32) * 80;

        #pragma unroll
        for (int ks = 0; ks < 2; ks++) {
            const uint32_t kb = ks * 32;
            uint32_t bh[4][2], bl[4][2];
            #pragma unroll
            for (int p = 0; p < 2; p++) {
                uint32_t base = bB + (uint32_t)(p * 16) * 80 + kb;
                LDSM_X4(bh[2*p][0], bh[2*p][1], bh[2*p+1][0], bh[2*p+1][1], base + loffB);
                LDSM_X4(bl[2*p][0], bl[2*p][1], bl[2*p+1][0], bl[2*p+1][1], base + TILB + loffB);
            }
            #pragma unroll
            for (int mt = 0; mt < 4; mt++) {
                uint32_t abase = aB + (uint32_t)(mt * 16) * 80 + kb;
                uint32_t ah[4], al[4];
                LDSM_X4(ah[0], ah[1], ah[2], ah[3], abase + loffA);
                LDSM_X4(al[0], al[1], al[2], al[3], abase + TILB + loffA);
                #pragma unroll
                for (int nt = 0; nt < 4; nt++) {
                    mma_bf16(acc[mt][nt], ah, bh[nt]);
                    mma_bf16(acc[mt][nt], ah, bl[nt]);
                    mma_bf16(acc[mt][nt], al, bh[nt]);
                }
            }
        }
        __syncthreads();
        if (c + 2 < nk) { prefetch(c + 2, st); CP_COMMIT(); }
    }

    #pragma unroll
    for (int mt = 0; mt < 4; mt++) {
        #pragma unroll
        for (int nt = 0; nt < 4; nt++) {
            int r = row0 + wm * 64 + mt * 16 + g;
            int c = col0 + wn * 32 + nt * 8 + 2 * t4;
            float2 v0 = make_float2(acc[mt][nt][0], acc[mt][nt][1]);
            float2 v1 = make_float2(acc[mt][nt][2], acc[mt][nt][3]);
            if (MODE == 0) {
                *(float2*)(C + (size_t)r * 1024 + c)       = v0;
                *(float2*)(C + (size_t)(r + 8) * 1024 + c) = v1;
            } else {
                int b_ = r >> 10, lr = r & 1023;
                int h_ = c >> 6,  d_ = c & 63;
                size_t base = ((size_t)(b_ * 16 + h_) * 1024) * 64 + d_;
                size_t i0 = base + (size_t)lr * 64;
                size_t i1 = base + (size_t)(lr + 8) * 64;
                *(float2*)(C + i0) = v0;
                *(float2*)(C + i1) = v1;
                if (Ehi) {
                    uint32_t h0, l0w, h1, l1w;
                    split_pack(v0.x, v0.y, h0, l0w);
                    split_pack(v1.x, v1.y, h1, l1w);
                    *(uint32_t*)(Ehi + i0) = h0;
                    *(uint32_t*)(Elo + i0) = l0w;
                    *(uint32_t*)(Ehi + i1) = h1;
                    *(uint32_t*)(Elo + i1) = l1w;
                }
            }
        }
    }
}

__global__ __launch_bounds__(256, 2) void gemm_qkv_k(
    const __nv_bfloat16* __restrict__ Ahi, const __nv_bfloat16* __restrict__ Alo,
    const __nv_bfloat16* __restrict__ Whi, const __nv_bfloat16* __restrict__ Wlo,
    float* __restrict__ Q, float* __restrict__ K, float* __restrict__ V,
    __nv_bfloat16* __restrict__ kbhi, __nv_bfloat16* __restrict__ kblo,
    __nv_bfloat16* __restrict__ vbhi, __nv_bfloat16* __restrict__ vblo)
{
    extern __shared__ char smem[];
    const int z = blockIdx.z;
    const size_t AO = (size_t)OUT_ELEMS, WO = (size_t)DIMn * DIMn;
    float* C = (z == 0) ? Q : (z == 1) ? K : V;
    __nv_bfloat16* Ehi = (z == 0) ? nullptr : (z == 1) ? kbhi : vbhi;
    __nv_bfloat16* Elo = (z == 0) ? nullptr : (z == 1) ? kblo : vblo;
    gemm_body<1>(Ahi + z * AO, Alo + z * AO, Whi + z * WO, Wlo + z * WO, C, Ehi, Elo, smem);
}

__global__ __launch_bounds__(256, 2) void gemm_out_k(
    const __nv_bfloat16* __restrict__ Ahi, const __nv_bfloat16* __restrict__ Alo,
    const __nv_bfloat16* __restrict__ Whi, const __nv_bfloat16* __restrict__ Wlo,
    float* __restrict__ C)
{
    extern __shared__ char smem[];
    gemm_body<0>(Ahi, Alo, Whi, Wlo, C, nullptr, nullptr, smem);
}

// ===========================================================================
// Even-head attention v7: S kept entirely in registers (no S smem buffer),
// register softmax with shfl + 8-warp smem partials, occ 2.
// Smem (bytes):
//   KV ring 4 x 18432  @0      73728
//   P 2 slots x 9216   @73728  18432
//   AUX 9216           @92160  (Qs [32][68] fp32 / softmax partials / red [32][72])
// total 101376 -> 2 CTAs/SM
// ===========================================================================
#define AE_KV   0
#define AE_TL   9216
#define AE_KVST 18432
#define AE_P    73728
#define AE_PTL  4608
#define AE_PST  9216
#define AE_AUX  92160
#define SMEM_EVEN 101376

__global__ __launch_bounds__(512, 2) void attn_even_k(
    const float* __restrict__ Qh,
    const __nv_bfloat16* __restrict__ Kbhi, const __nv_bfloat16* __restrict__ Kblo,
    const __nv_bfloat16* __restrict__ Vbhi, const __nv_bfloat16* __restrict__ Vblo,
    const float* __restrict__ mask_s,
    float* __restrict__ attn_s,
    __nv_bfloat16* __restrict__ cat_hi, __nv_bfloat16* __restrict__ cat_lo)
{
    extern __shared__ char smem[];
    float* Qs   = (float*)(smem + AE_AUX);   // [32][68] fp32 (init phase only)
    float* part = (float*)(smem + AE_AUX);   // [32][8] softmax partials
    float* red  = (float*)(smem + AE_AUX);   // [32][72] PV reduction
    uint32_t sb;
    asm("{ .reg .u64 u; cvta.to.shared.u64 u, %1; cvt.u32.u64 %0, u; }" : "=r"(sb) : "l"(smem));

    const int qt = blockIdx.x, j = blockIdx.y, b = blockIdx.z;
    const int h = 2 * j;
    const int tid = threadIdx.x;
    const int warp = tid >> 5, lane = tid & 31;
    const int g = lane >> 2, t4 = lane & 3;
    const int mt = warp >> 3, ntw = warp & 7;
    const int m0 = mt * 16, n0 = ntw * 8;
    const size_t headoff = (size_t)(b * 16 + h) * 1024 * 64;
    const float* Qb = Qh + headoff;
    const int r0 = qt * 32;

    const int krow = tid >> 3, kc16 = tid & 7;
    const uint32_t kvdst = (uint32_t)(krow * 144 + kc16 * 16);
    const size_t   kvsrc0 = (headoff + (size_t)krow * 64 + kc16 * 8) * 2;

    auto prefT = [&](const __nv_bfloat16* Hhi, const __nv_bfloat16* Hlo, int kt, int slot) {
        uint32_t d = sb + AE_KV + (uint32_t)slot * AE_KVST + kvdst;
        size_t s = kvsrc0 + (size_t)kt * 64 * 64 * 2;
        CP_ASYNC16(d,         (const char*)Hhi + s);
        CP_ASYNC16(d + AE_TL, (const char*)Hlo + s);
    };

    prefT(Kbhi, Kblo, 0, 0); CP_COMMIT();
    prefT(Kbhi, Kblo, 1, 1); CP_COMMIT();
    {
        int r = tid >> 4, c = (tid & 15) * 4;
        float4 v = *(const float4*)(Qb + (size_t)(r0 + r) * 64 + c);
        *(float4*)&Qs[r * 68 + c] = v;
    }
    __syncthreads();

    uint32_t qhF[4][4], qlF[4][4];
    #pragma unroll
    for (int ks = 0; ks < 4; ks++) {
        int kc = ks * 16 + 2 * t4;
        split_pack(Qs[(m0+g)*68 + kc],     Qs[(m0+g)*68 + kc + 1],     qhF[ks][0], qlF[ks][0]);
        split_pack(Qs[(m0+g+8)*68 + kc],   Qs[(m0+g+8)*68 + kc + 1],   qhF[ks][1], qlF[ks][1]);
        split_pack(Qs[(m0+g)*68 + kc + 8], Qs[(m0+g)*68 + kc + 9],     qhF[ks][2], qlF[ks][2]);
        split_pack(Qs[(m0+g+8)*68 + kc+8], Qs[(m0+g+8)*68 + kc + 9],   qhF[ks][3], qlF[ks][3]);
    }
    __syncthreads();   // Q frags built before AUX region is reused

    const int lrow = (lane & 7);
    const uint32_t lsel4 = (uint32_t)((lane >> 3) * 16);

    const float* mrow0 = mask_s + (size_t)(r0 + m0 + g) * 1024 + n0 + 2 * t4;
    const float* mrow1 = mask_s + (size_t)(r0 + m0 + g + 8) * 1024 + n0 + 2 * t4;

    float2 mk0 = *(const float2*)(mrow0);
    float2 mk1 = *(const float2*)(mrow1);

    // ---- S = Q K^T over 16 K tiles, results kept in registers ----
    float Sreg[16][4];
    #pragma unroll
    for (int kt = 0; kt < 16; kt++) {
        const int st = kt % 3;
        if (kt < 15) { CP_WAIT(1); } else { CP_WAIT(0); }
        __syncthreads();

        float2 nk0, nk1;
        if (kt < 15) {
            nk0 = *(const float2*)(mrow0 + (kt + 1) * 64);
            nk1 = *(const float2*)(mrow1 + (kt + 1) * 64);
        }

        float accS[4] = {0.f, 0.f, 0.f, 0.f};
        const uint32_t kb_hi = sb + AE_KV + (uint32_t)st * AE_KVST;
        uint32_t bh[4][2], bl[4][2];
        #pragma unroll
        for (int kp = 0; kp < 2; kp++) {
            uint32_t addr = kb_hi + (uint32_t)(n0 + lrow) * 144 + kp * 64 + lsel4;
            LDSM_X4(bh[2*kp][0], bh[2*kp][1], bh[2*kp+1][0], bh[2*kp+1][1], addr);
            LDSM_X4(bl[2*kp][0], bl[2*kp][1], bl[2*kp+1][0], bl[2*kp+1][1], addr + AE_TL);
        }
        #pragma unroll
        for (int ks = 0; ks < 4; ks++) {
            mma_bf16(accS, qhF[ks], bh[ks]);
            mma_bf16(accS, qhF[ks], bl[ks]);
            mma_bf16(accS, qlF[ks], bh[ks]);
        }
        Sreg[kt][0] = accS[0] * 0.125f + mk0.x;
        Sreg[kt][1] = accS[1] * 0.125f + mk0.y;
        Sreg[kt][2] = accS[2] * 0.125f + mk1.x;
        Sreg[kt][3] = accS[3] * 0.125f + mk1.y;
        mk0 = nk0; mk1 = nk1;

        if (kt + 2 < 16) { prefT(Kbhi, Kblo, kt + 2, (kt + 2) % 3); CP_COMMIT(); }
    }
    __syncthreads();

    // Start V pipeline (two streams, 4-slot ring)
    auto vslot = [](int kt) { return (kt < 8) ? (kt & 1) : 2 + (kt & 1); };
    prefT(Vbhi, Vblo, 0, vslot(0));
    prefT(Vbhi, Vblo, 8, vslot(8));
    CP_COMMIT();

    // ---- register softmax ----
    float mx0 = -1e30f, mx1 = -1e30f;
    #pragma unroll
    for (int kt = 0; kt < 16; kt++) {
        mx0 = fmaxf(mx0, fmaxf(Sreg[kt][0], Sreg[kt][1]));
        mx1 = fmaxf(mx1, fmaxf(Sreg[kt][2], Sreg[kt][3]));
    }
    mx0 = fmaxf(mx0, __shfl_xor_sync(0xffffffffu, mx0, 1));
    mx0 = fmaxf(mx0, __shfl_xor_sync(0xffffffffu, mx0, 2));
    mx1 = fmaxf(mx1, __shfl_xor_sync(0xffffffffu, mx1, 1));
    mx1 = fmaxf(mx1, __shfl_xor_sync(0xffffffffu, mx1, 2));
    if (t4 == 0) {
        part[(m0 + g) * 8 + ntw]     = mx0;
        part[(m0 + g + 8) * 8 + ntw] = mx1;
    }
    __syncthreads();
    #pragma unroll
    for (int w = 0; w < 8; w++) {
        mx0 = fmaxf(mx0, part[(m0 + g) * 8 + w]);
        mx1 = fmaxf(mx1, part[(m0 + g + 8) * 8 + w]);
    }
    __syncthreads();

    float sum0 = 0.f, sum1 = 0.f;
    #pragma unroll
    for (int kt = 0; kt < 16; kt++) {
        Sreg[kt][0] = __expf(Sreg[kt][0] - mx0);
        Sreg[kt][1] = __expf(Sreg[kt][1] - mx0);
        Sreg[kt][2] = __expf(Sreg[kt][2] - mx1);
        Sreg[kt][3] = __expf(Sreg[kt][3] - mx1);
        sum0 += Sreg[kt][0] + Sreg[kt][1];
        sum1 += Sreg[kt][2] + Sreg[kt][3];
    }
    sum0 += __shfl_xor_sync(0xffffffffu, sum0, 1);
    sum0 += __shfl_xor_sync(0xffffffffu, sum0, 2);
    sum1 += __shfl_xor_sync(0xffffffffu, sum1, 1);
    sum1 += __shfl_xor_sync(0xffffffffu, sum1, 2);
    if (t4 == 0) {
        part[(m0 + g) * 8 + ntw]     = sum0;
        part[(m0 + g + 8) * 8 + ntw] = sum1;
    }
    __syncthreads();
    float tot0 = 0.f, tot1 = 0.f;
    #pragma unroll
    for (int w = 0; w < 8; w++) {
        tot0 += part[(m0 + g) * 8 + w];
        tot1 += part[(m0 + g + 8) * 8 + w];
    }
    const float inv0 = 1.f / tot0;
    const float inv1 = 1.f / tot1;
    __syncthreads();   // part region free for red reuse later

    // ---- write attn_s from registers (streaming) ----
    {
        float* arow0 = attn_s + ((size_t)(b * 8 + j) * 1024 + r0 + m0 + g) * 1024 + n0 + 2 * t4;
        float* arow1 = attn_s + ((size_t)(b * 8 + j) * 1024 + r0 + m0 + g + 8) * 1024 + n0 + 2 * t4;
        #pragma unroll
        for (int kt = 0; kt < 16; kt++) {
            __stcs((float2*)(arow0 + kt * 64), make_float2(Sreg[kt][0] * inv0, Sreg[kt][1] * inv0));
            __stcs((float2*)(arow1 + kt * 64), make_float2(Sreg[kt][2] * inv1, Sreg[kt][3] * inv1));
        }
    }

    // ---- O = P V: 2 kh x 2 mt2 x 2 n-tiles/warp; P stored from registers ----
    const int kh   = warp >> 3;
    const int mt2  = (warp >> 2) & 1;
    const int nn   = warp & 3;
    const int pm0  = mt2 * 16;
    const int pn0  = nn * 16;

    float accO[2][4];
    #pragma unroll
    for (int n = 0; n < 2; n++)
        #pragma unroll
        for (int i = 0; i < 4; i++) accO[n][i] = 0.f;

    const int sub = lane >> 3, r8 = lane & 7;
    const uint32_t poff = (uint32_t)((pm0 + r8 + (sub & 1) * 8) * 144 + (sub >> 1) * 16);
    const int vrow = (lane & 15);

    // P store addresses for this thread (own rows/cols)
    char* pst0 = smem + AE_P + (m0 + g) * 144 + (n0 + 2 * t4) * 2;
    char* pst1 = smem + AE_P + (m0 + g + 8) * 144 + (n0 + 2 * t4) * 2;

    #pragma unroll
    for (int it = 0; it < 8; it++) {
        // store P tiles (kt=it -> slot 0, kt=it+8 -> slot 1) from registers
        {
            uint32_t h0, l0, h1, l1;
            split_pack(Sreg[it][0] * inv0, Sreg[it][1] * inv0, h0, l0);
            split_pack(Sreg[it][2] * inv1, Sreg[it][3] * inv1, h1, l1);
            *(uint32_t*)pst0            = h0;
            *(uint32_t*)(pst0 + AE_PTL) = l0;
            *(uint32_t*)pst1            = h1;
            *(uint32_t*)(pst1 + AE_PTL) = l1;
            split_pack(Sreg[it+8][0] * inv0, Sreg[it+8][1] * inv0, h0, l0);
            split_pack(Sreg[it+8][2] * inv1, Sreg[it+8][3] * inv1, h1, l1);
            *(uint32_t*)(pst0 + AE_PST)            = h0;
            *(uint32_t*)(pst0 + AE_PST + AE_PTL)   = l0;
            *(uint32_t*)(pst1 + AE_PST)            = h1;
            *(uint32_t*)(pst1 + AE_PST + AE_PTL)   = l1;
        }
        if (it < 7) {
            prefT(Vbhi, Vblo, it + 1, vslot(it + 1));
            prefT(Vbhi, Vblo, it + 9, vslot(it + 9));
            CP_COMMIT();
            CP_WAIT(1);
        } else {
            CP_WAIT(0);
        }
        __syncthreads();

        const int ktw = kh * 8 + it;
        const uint32_t pb = sb + AE_P + (uint32_t)kh * AE_PST;
        const uint32_t vb = sb + AE_KV + (uint32_t)vslot(ktw) * AE_KVST;
        #pragma unroll
        for (int ks = 0; ks < 4; ks++) {
            uint32_t ph[4], pl[4];
            LDSM_X4(ph[0], ph[1], ph[2], ph[3], pb + poff + ks * 32);
            LDSM_X4(pl[0], pl[1], pl[2], pl[3], pb + AE_PTL + poff + ks * 32);
            uint32_t vrbase = vb + (uint32_t)(ks * 16 + vrow) * 144;
            #pragma unroll
            for (int n = 0; n < 2; n++) {
                uint32_t vh[2], vl[2];
                uint32_t va = vrbase + (uint32_t)(pn0 + n * 8) * 2;
                LDSM_X2_T(vh[0], vh[1], va);
                LDSM_X2_T(vl[0], vl[1], va + AE_TL);
                mma_bf16(accO[n], ph, vh);
                mma_bf16(accO[n], ph, vl);
                mma_bf16(accO[n], pl, vh);
            }
        }
        __syncthreads();
    }

    // ---- reduce kt-half partials via smem, store cat bf16 hi/lo ----
    if (kh == 1) {
        #pragma unroll
        for (int n = 0; n < 2; n++) {
            int c = pn0 + n * 8 + 2 * t4;
            *(float2*)&red[(pm0 + g) * 72 + c]     = make_float2(accO[n][0], accO[n][1]);
            *(float2*)&red[(pm0 + g + 8) * 72 + c] = make_float2(accO[n][2], accO[n][3]);
        }
    }
    __syncthreads();
    if (kh == 0) {
        #pragma unroll
        for (int n = 0; n < 2; n++) {
            int c = pn0 + n * 8 + 2 * t4;
            float2 p0 = *(const float2*)&red[(pm0 + g) * 72 + c];
            float2 p1 = *(const float2*)&red[(pm0 + g + 8) * 72 + c];
            float o0 = accO[n][0] + p0.x, o1 = accO[n][1] + p0.y;
            float o2 = accO[n][2] + p1.x, o3 = accO[n][3] + p1.y;
            int cc = j * 64 + c;
            size_t i0 = ((size_t)b * 1024 + r0 + pm0 + g) * 1024 + cc;
            size_t i1 = ((size_t)b * 1024 + r0 + pm0 + g + 8) * 1024 + cc;
            uint32_t h0, l0, h1, l1;
            split_pack(o0, o1, h0, l0);
            split_pack(o2, o3, h1, l1);
            *(uint32_t*)(cat_hi + i0) = h0;
            *(uint32_t*)(cat_lo + i0) = l0;
            *(uint32_t*)(cat_hi + i1) = h1;
            *(uint32_t*)(cat_lo + i1) = l1;
        }
    }
}

// ---------------------------------------------------------------------------
// Odd-head "feature" attention (unchanged; cat emitted as bf16 hi/lo).
// ---------------------------------------------------------------------------
#define SMEM_FEAT ((2*64*64 + 64*65) * 4)
__global__ __launch_bounds__(512) void attn_feat_k(
    const float* __restrict__ Qh, const float* __restrict__ Kh,
    const float* __restrict__ Vh, const float* __restrict__ mask_f,
    float* __restrict__ attn_f,
    __nv_bfloat16* __restrict__ cat_hi, __nv_bfloat16* __restrict__ cat_lo)
{
    extern __shared__ float sm[];
    float* Qt  = sm;
    float* Kt  = Qt + 4096;
    float* Asm = Kt + 4096;

    const int jp = blockIdx.x, b = blockIdx.y;
    const int h = 2 * jp + 1;
    const int tid = threadIdx.x;
    const size_t headoff = (size_t)(b * 16 + h) * 1024 * 64;
    const float* Qb = Qh + headoff;
    const float* Kb = Kh + headoff;
    const float* Vb = Vh + headoff;

    const int m  = tid & 63;
    const int g8 = tid >> 6;

    float acc[8];
    #pragma unroll
    for (int i = 0; i < 8; i++) acc[i] = 0.f;

    for (int lt = 0; lt < 16; lt++) {
        __syncthreads();
        for (int i = tid; i < 1024; i += 512) {
            ((float4*)Qt)[i] = ((const float4*)(Qb + (size_t)lt * 4096))[i];
            ((float4*)Kt)[i] = ((const float4*)(Kb + (size_t)lt * 4096))[i];
        }
        __syncthreads();
        for (int ll = 0; ll < 64; ll++) {
            float kk = Kt[ll * 64 + m];
            #pragma unroll
            for (int i = 0; i < 8; i++)
                acc[i] = fmaf(Qt[ll * 64 + g8 + 8 * i], kk, acc[i]);
        }
    }
    __syncthreads();
    #pragma unroll
    for (int i = 0; i < 8; i++) {
        int n = g8 + 8 * i;
        Asm[n * 65 + m] = acc[i] * 0.125f + mask_f[n * 64 + m];
    }
    __syncthreads();

    const int warp = tid >> 5, lane = tid & 31;
    for (int n = warp * 4; n < warp * 4 + 4; n++) {
        float* row = Asm + n * 65;
        float a0 = row[lane], a1 = row[lane + 32];
        float mx = fmaxf(a0, a1);
        #pragma unroll
        for (int o = 16; o > 0; o >>= 1) mx = fmaxf(mx, __shfl_xor_sync(0xffffffffu, mx, o));
        float e0 = __expf(a0 - mx), e1 = __expf(a1 - mx);
        float s = e0 + e1;
        #pragma unroll
        for (int o = 16; o > 0; o >>= 1) s += __shfl_xor_sync(0xffffffffu, s, o);
        float inv = 1.f / s;
        e0 *= inv; e1 *= inv;
        row[lane] = e0; row[lane + 32] = e1;
        float* grow = attn_f + ((size_t)(b * 8 + jp) * 64 + n) * 64;
        grow[lane] = e0; grow[lane + 32] = e1;
    }
    __syncthreads();

    float* Vt = Qt;
    const int n2 = m;
    for (int lt = 0; lt < 16; lt++) {
        __syncthreads();
        for (int i = tid; i < 1024; i += 512)
            ((float4*)Vt)[i] = ((const float4*)(Vb + (size_t)lt * 4096))[i];
        __syncthreads();

        float accO[8];
        #pragma unroll
        for (int i = 0; i < 8; i++) accO[i] = 0.f;
        for (int mm = 0; mm < 64; mm++) {
            float aa = Asm[n2 * 65 + mm];
            #pragma unroll
            for (int i = 0; i < 8; i++)
                accO[i] = fmaf(Vt[(g8 + 8 * i) * 64 + mm], aa, accO[i]);
        }
        #pragma unroll
        for (int i = 0; i < 8; i++) {
            int ll = g8 + 8 * i;
            size_t idx = ((size_t)b * 1024 + lt * 64 + ll) * 1024 + (8 + jp) * 64 + n2;
            float x = accO[i];
            __nv_bfloat16 hb = __float2bfloat16(x);
            __nv_bfloat16 lb = __float2bfloat16(x - __bfloat162float(hb));
            cat_hi[idx] = hb;
            cat_lo[idx] = lb;
        }
    }
}

// ---------------------------------------------------------------------------
extern "C" void kernel_launch(void* const* d_in, const int* in_sizes, int n_in,
                              void* d_out, int out_size)
{
    const float* q      = (const float*)d_in[0];
    const float* k      = (const float*)d_in[1];
    const float* v      = (const float*)d_in[2];
    const float* mask_s = (const float*)d_in[3];
    const float* mask_f = (const float*)d_in[4];
    const float* Wq     = (const float*)d_in[5];
    const float* Wk     = (const float*)d_in[6];
    const float* Wv     = (const float*)d_in[7];
    const float* Wo     = (const float*)d_in[8];

    float* out    = (float*)d_out;
    float* attn_s = out + OUT_ELEMS;
    float* attn_f = attn_s + ATTNS_ELEMS;

    float *qh, *kh, *vh;
    __nv_bfloat16 *ahi, *alo, *whi, *wlo, *kbhi, *kblo, *vbhi, *vblo;
    cudaGetSymbolAddress((void**)&qh,  g_qh);
    cudaGetSymbolAddress((void**)&kh,  g_kh);
    cudaGetSymbolAddress((void**)&vh,  g_vh);
    cudaGetSymbolAddress((void**)&ahi, g_ahi3);
    cudaGetSymbolAddress((void**)&alo, g_alo3);
    cudaGetSymbolAddress((void**)&whi, g_whi4);
    cudaGetSymbolAddress((void**)&wlo, g_wlo4);
    cudaGetSymbolAddress((void**)&kbhi, g_kbhi);
    cudaGetSymbolAddress((void**)&kblo, g_kblo);
    cudaGetSymbolAddress((void**)&vbhi, g_vbhi);
    cudaGetSymbolAddress((void**)&vblo, g_vblo);

    cudaFuncSetAttribute(attn_even_k, cudaFuncAttributeMaxDynamicSharedMemorySize, SMEM_EVEN);
    cudaFuncSetAttribute(attn_feat_k, cudaFuncAttributeMaxDynamicSharedMemorySize, SMEM_FEAT);
    cudaFuncSetAttribute(gemm_qkv_k, cudaFuncAttributeMaxDynamicSharedMemorySize, GSMEM);
    cudaFuncSetAttribute(gemm_out_k, cudaFuncAttributeMaxDynamicSharedMemorySize, GSMEM);

    dim3 ggrid3(DIMn / 128, (Bn * Ln) / 128, 3);
    dim3 ggrid(DIMn / 128, (Bn * Ln) / 128);
    dim3 sgrid3(OUT_ELEMS / (256 * 4), 3);
    dim3 wgrid4(32, 32, 4), wblk(32, 8);

    const size_t WO = (size_t)DIMn * DIMn;

    split_a3_k<<<sgrid3, 256>>>(q, k, v, ahi, alo);
    split_w4_k<<<wgrid4, wblk>>>(Wq, Wk, Wv, Wo, whi, wlo);

    gemm_qkv_k<<<ggrid3, 256, GSMEM>>>(ahi, alo, whi, wlo, qh, kh, vh,
                                       kbhi, kblo, vbhi, vblo);

    attn_even_k<<<dim3(32, 8, 16), 512, SMEM_EVEN>>>(qh, kbhi, kblo, vbhi, vblo,
                                                     mask_s, attn_s, ahi, alo);
    attn_feat_k<<<dim3(8, 16), 512, SMEM_FEAT>>>(qh, kh, vh, mask_f, attn_f, ahi, alo);

    gemm_out_k<<<ggrid, 256, GSMEM>>>(ahi, alo, whi + 3 * WO, wlo + 3 * WO, out);
}

// round 16
// speedup vs baseline: 1.1088x; 1.1088x over previous
#include <cuda_runtime.h>
#include <cuda_bf16.h>
#include <cstdint>
#include <cstddef>

// Problem constants
#define Bn   16
#define Ln   1024
#define DIMn 1024
#define NH   16
#define DK   64

#define OUT_ELEMS    (16*1024*1024)
#define ATTNS_ELEMS  (16*8*1024*1024)
#define ATTNF_ELEMS  (16*8*64*64)

// fp32 scratch (head-major Qh/Kh/Vh)
__device__ float g_qh[OUT_ELEMS];
__device__ float g_kh[OUT_ELEMS];
__device__ float g_vh[OUT_ELEMS];
// bf16 split scratch: 3 activation tensors + 4 weights
__device__ __nv_bfloat16 g_ahi3[3*OUT_ELEMS];
__device__ __nv_bfloat16 g_alo3[3*OUT_ELEMS];
__device__ __nv_bfloat16 g_whi4[4*DIMn*DIMn];
__device__ __nv_bfloat16 g_wlo4[4*DIMn*DIMn];
// bf16 head-major K/V echoed by the QKV GEMM epilogue
__device__ __nv_bfloat16 g_kbhi[OUT_ELEMS];
__device__ __nv_bfloat16 g_kblo[OUT_ELEMS];
__device__ __nv_bfloat16 g_vbhi[OUT_ELEMS];
__device__ __nv_bfloat16 g_vblo[OUT_ELEMS];

// ===========================================================================
// Common helpers
// ===========================================================================
#define CP_ASYNC16(dst, src) \
    asm volatile("cp.async.cg.shared.global [%0], [%1], 16;\n" :: "r"(dst), "l"(src))
#define CP_COMMIT() asm volatile("cp.async.commit_group;\n" ::: "memory")
#define CP_WAIT(n)  asm volatile("cp.async.wait_group %0;\n" :: "n"(n) : "memory")

#define LDSM_X4(r0, r1, r2, r3, addr) \
    asm volatile("ldmatrix.sync.aligned.m8n8.x4.shared.b16 {%0,%1,%2,%3}, [%4];" \
                 : "=r"(r0), "=r"(r1), "=r"(r2), "=r"(r3) : "r"(addr))
#define LDSM_X2_T(r0, r1, addr) \
    asm volatile("ldmatrix.sync.aligned.m8n8.x2.trans.shared.b16 {%0,%1}, [%2];" \
                 : "=r"(r0), "=r"(r1) : "r"(addr))

__device__ __forceinline__ void mma_bf16(float c[4], const uint32_t a[4], const uint32_t b[2]) {
    asm volatile(
        "mma.sync.aligned.m16n8k16.row.col.f32.bf16.bf16.f32 "
        "{%0,%1,%2,%3}, {%4,%5,%6,%7}, {%8,%9}, {%0,%1,%2,%3};\n"
        : "+f"(c[0]), "+f"(c[1]), "+f"(c[2]), "+f"(c[3])
        : "r"(a[0]), "r"(a[1]), "r"(a[2]), "r"(a[3]), "r"(b[0]), "r"(b[1]));
}

static __device__ __forceinline__ void split_pack(float x0, float x1,
                                                  uint32_t& hi, uint32_t& lo) {
    __nv_bfloat16 h0 = __float2bfloat16(x0);
    __nv_bfloat16 h1 = __float2bfloat16(x1);
    __nv_bfloat16 l0 = __float2bfloat16(x0 - __bfloat162float(h0));
    __nv_bfloat16 l1 = __float2bfloat16(x1 - __bfloat162float(h1));
    __nv_bfloat162 hp(h0, h1), lp(l0, l1);
    hi = *reinterpret_cast<uint32_t*>(&hp);
    lo = *reinterpret_cast<uint32_t*>(&lp);
}

// ===========================================================================
// Split kernels (fp32 -> bf16 hi/lo)
// ===========================================================================
__global__ __launch_bounds__(256) void split_a3_k(
    const float* __restrict__ X0, const float* __restrict__ X1,
    const float* __restrict__ X2,
    __nv_bfloat16* __restrict__ hi, __nv_bfloat16* __restrict__ lo)
{
    const int t = blockIdx.y;
    const float* X = (t == 0) ? X0 : (t == 1) ? X1 : X2;
    size_t obase = (size_t)t * OUT_ELEMS;
    int i = (blockIdx.x * 256 + threadIdx.x) * 4;
    float4 v = *(const float4*)(X + i);
    float x[4] = {v.x, v.y, v.z, v.w};
    __nv_bfloat16 h[4], l[4];
    #pragma unroll
    for (int j = 0; j < 4; j++) {
        h[j] = __float2bfloat16(x[j]);
        l[j] = __float2bfloat16(x[j] - __bfloat162float(h[j]));
    }
    __nv_bfloat162* hp = (__nv_bfloat162*)(hi + obase + i);
    __nv_bfloat162* lp = (__nv_bfloat162*)(lo + obase + i);
    hp[0] = __nv_bfloat162{h[0], h[1]}; hp[1] = __nv_bfloat162{h[2], h[3]};
    lp[0] = __nv_bfloat162{l[0], l[1]}; lp[1] = __nv_bfloat162{l[2], l[3]};
}

__global__ __launch_bounds__(256) void split_w4_k(
    const float* __restrict__ W0, const float* __restrict__ W1,
    const float* __restrict__ W2, const float* __restrict__ W3,
    __nv_bfloat16* __restrict__ hi, __nv_bfloat16* __restrict__ lo)
{
    __shared__ float t[32][33];
    const int wz = blockIdx.z;
    const float* W = (wz == 0) ? W0 : (wz == 1) ? W1 : (wz == 2) ? W2 : W3;
    size_t obase = (size_t)wz * DIMn * DIMn;
    const int tx = threadIdx.x, ty = threadIdx.y;
    const int n0 = blockIdx.x * 32, k0 = blockIdx.y * 32;
    #pragma unroll
    for (int j = 0; j < 32; j += 8)
        t[ty + j][tx] = W[(size_t)(k0 + ty + j) * DIMn + n0 + tx];
    __syncthreads();
    #pragma unroll
    for (int j = 0; j < 32; j += 8) {
        int n = n0 + ty + j, kk = k0 + tx;
        float x = t[tx][ty + j];
        __nv_bfloat16 h = __float2bfloat16(x);
        __nv_bfloat16 l = __float2bfloat16(x - __bfloat162float(h));
        hi[obase + (size_t)n * DIMn + kk] = h;
        lo[obase + (size_t)n * DIMn + kk] = l;
    }
}

// ===========================================================================
// Split-bf16 mma.sync GEMM mainloop (PASSING, unchanged).
// ===========================================================================
#define RS      40
#define TILB    (128*RS*2)
#define STAGEB  (4*TILB)
#define GSMEM   (2*STAGEB)

template<int MODE>
__device__ __forceinline__ void gemm_body(
    const __nv_bfloat16* __restrict__ Ahi, const __nv_bfloat16* __restrict__ Alo,
    const __nv_bfloat16* __restrict__ Bhi, const __nv_bfloat16* __restrict__ Blo,
    float* __restrict__ C, __nv_bfloat16* __restrict__ Ehi,
    __nv_bfloat16* __restrict__ Elo, char* smem)
{
    uint32_t sb;
    asm("{ .reg .u64 u; cvta.to.shared.u64 u, %1; cvt.u32.u64 %0, u; }" : "=r"(sb) : "l"(smem));

    const int tid  = threadIdx.x;
    const int lane = tid & 31;
    const int warp = tid >> 5;
    const int wm   = warp >> 2;
    const int wn   = warp & 3;
    const int g    = lane >> 2;
    const int t4   = lane & 3;

    const int row0 = blockIdx.y * 128;
    const int col0 = blockIdx.x * 128;

    const int sub = lane >> 3, r8 = lane & 7;
    const uint32_t loffA = (uint32_t)((r8 + (sub & 1) * 8) * 80 + (sub >> 1) * 16);
    const uint32_t loffB = (uint32_t)((r8 + (sub >> 1) * 8) * 80 + (sub & 1) * 16);

    const int ra = tid >> 2, ca = tid & 3;
    const int rb = (tid + 256) >> 2, cb = ca;

    auto prefetch = [&](int c, int st) {
        const int kc = c * 32;
        uint32_t s0 = sb + (uint32_t)st * STAGEB;
        {
            uint32_t d = s0 + (uint32_t)(ra * 80 + ca * 16);
            size_t ga = ((size_t)(row0 + ra) * 1024 + kc + ca * 8) * 2;
            size_t gb = ((size_t)(col0 + ra) * 1024 + kc + ca * 8) * 2;
            CP_ASYNC16(d,            (const char*)Ahi + ga);
            CP_ASYNC16(d + TILB,     (const char*)Alo + ga);
            CP_ASYNC16(d + 2*TILB,   (const char*)Bhi + gb);
            CP_ASYNC16(d + 3*TILB,   (const char*)Blo + gb);
        }
        {
            uint32_t d = s0 + (uint32_t)(rb * 80 + cb * 16);
            size_t ga = ((size_t)(row0 + rb) * 1024 + kc + cb * 8) * 2;
            size_t gb = ((size_t)(col0 + rb) * 1024 + kc + cb * 8) * 2;
            CP_ASYNC16(d,            (const char*)Ahi + ga);
            CP_ASYNC16(d + TILB,     (const char*)Alo + ga);
            CP_ASYNC16(d + 2*TILB,   (const char*)Bhi + gb);
            CP_ASYNC16(d + 3*TILB,   (const char*)Blo + gb);
        }
    };

    float acc[4][4][4];
    #pragma unroll
    for (int mt = 0; mt < 4; mt++)
        #pragma unroll
        for (int nt = 0; nt < 4; nt++)
            #pragma unroll
            for (int i = 0; i < 4; i++) acc[mt][nt][i] = 0.f;

    prefetch(0, 0); CP_COMMIT();
    prefetch(1, 1); CP_COMMIT();

    const int nk = 32;
    for (int c = 0; c < nk; c++) {
        const int st = c & 1;
        if (c + 1 < nk) { CP_WAIT(1); } else { CP_WAIT(0); }
        __syncthreads();

        const uint32_t s0 = sb + (uint32_t)st * STAGEB;
        const uint32_t aB = s0 + (uint32_t)(wm * 64) * 80;
        const uint32_t bB = s0 + 2 * TILB + (uint32_t)(wn * 32) * 80;

        #pragma unroll
        for (int ks = 0; ks < 2; ks++) {
            const uint32_t kb = ks * 32;
            uint32_t bh[4][2], bl[4][2];
            #pragma unroll
            for (int p = 0; p < 2; p++) {
                uint32_t base = bB + (uint32_t)(p * 16) * 80 + kb;
                LDSM_X4(bh[2*p][0], bh[2*p][1], bh[2*p+1][0], bh[2*p+1][1], base + loffB);
                LDSM_X4(bl[2*p][0], bl[2*p][1], bl[2*p+1][0], bl[2*p+1][1], base + TILB + loffB);
            }
            #pragma unroll
            for (int mt = 0; mt < 4; mt++) {
                uint32_t abase = aB + (uint32_t)(mt * 16) * 80 + kb;
                uint32_t ah[4], al[4];
                LDSM_X4(ah[0], ah[1], ah[2], ah[3], abase + loffA);
                LDSM_X4(al[0], al[1], al[2], al[3], abase + TILB + loffA);
                #pragma unroll
                for (int nt = 0; nt < 4; nt++) {
                    mma_bf16(acc[mt][nt], ah, bh[nt]);
                    mma_bf16(acc[mt][nt], ah, bl[nt]);
                    mma_bf16(acc[mt][nt], al, bh[nt]);
                }
            }
        }
        __syncthreads();
        if (c + 2 < nk) { prefetch(c + 2, st); CP_COMMIT(); }
    }

    #pragma unroll
    for (int mt = 0; mt < 4; mt++) {
        #pragma unroll
        for (int nt = 0; nt < 4; nt++) {
            int r = row0 + wm * 64 + mt * 16 + g;
            int c = col0 + wn * 32 + nt * 8 + 2 * t4;
            float2 v0 = make_float2(acc[mt][nt][0], acc[mt][nt][1]);
            float2 v1 = make_float2(acc[mt][nt][2], acc[mt][nt][3]);
            if (MODE == 0) {
                *(float2*)(C + (size_t)r * 1024 + c)       = v0;
                *(float2*)(C + (size_t)(r + 8) * 1024 + c) = v1;
            } else {
                int b_ = r >> 10, lr = r & 1023;
                int h_ = c >> 6,  d_ = c & 63;
                size_t base = ((size_t)(b_ * 16 + h_) * 1024) * 64 + d_;
                size_t i0 = base + (size_t)lr * 64;
                size_t i1 = base + (size_t)(lr + 8) * 64;
                *(float2*)(C + i0) = v0;
                *(float2*)(C + i1) = v1;
                if (Ehi) {
                    uint32_t h0, l0w, h1, l1w;
                    split_pack(v0.x, v0.y, h0, l0w);
                    split_pack(v1.x, v1.y, h1, l1w);
                    *(uint32_t*)(Ehi + i0) = h0;
                    *(uint32_t*)(Elo + i0) = l0w;
                    *(uint32_t*)(Ehi + i1) = h1;
                    *(uint32_t*)(Elo + i1) = l1w;
                }
            }
        }
    }
}

__global__ __launch_bounds__(256, 2) void gemm_qkv_k(
    const __nv_bfloat16* __restrict__ Ahi, const __nv_bfloat16* __restrict__ Alo,
    const __nv_bfloat16* __restrict__ Whi, const __nv_bfloat16* __restrict__ Wlo,
    float* __restrict__ Q, float* __restrict__ K, float* __restrict__ V,
    __nv_bfloat16* __restrict__ kbhi, __nv_bfloat16* __restrict__ kblo,
    __nv_bfloat16* __restrict__ vbhi, __nv_bfloat16* __restrict__ vblo)
{
    extern __shared__ char smem[];
    const int z = blockIdx.z;
    const size_t AO = (size_t)OUT_ELEMS, WO = (size_t)DIMn * DIMn;
    float* C = (z == 0) ? Q : (z == 1) ? K : V;
    __nv_bfloat16* Ehi = (z == 0) ? nullptr : (z == 1) ? kbhi : vbhi;
    __nv_bfloat16* Elo = (z == 0) ? nullptr : (z == 1) ? kblo : vblo;
    gemm_body<1>(Ahi + z * AO, Alo + z * AO, Whi + z * WO, Wlo + z * WO, C, Ehi, Elo, smem);
}

__global__ __launch_bounds__(256, 2) void gemm_out_k(
    const __nv_bfloat16* __restrict__ Ahi, const __nv_bfloat16* __restrict__ Alo,
    const __nv_bfloat16* __restrict__ Whi, const __nv_bfloat16* __restrict__ Wlo,
    float* __restrict__ C)
{
    extern __shared__ char smem[];
    gemm_body<0>(Ahi, Alo, Whi, Wlo, C, nullptr, nullptr, smem);
}

// ===========================================================================
// Even-head attention v8: 16-row Q tile, 256 threads, occ 2.
// S in smem; pre-split K/V via 2-slot cp.async rings; R12-style PV.
// Smem (bytes):
//   Ssm fp32 [16][1028]  @0       65792
//   sinv [16] + pad      @65792   128
//   KV 2 slots x 18432   @65920   36864
//   P  2 slots x 4608    @102784  9216   (Qs [16][68] fp32 = 4352 aliases P)
// total 112000 -> 2 CTAs/SM
// ===========================================================================
#define SSTR    1028
#define AE_SINV 65792
#define AE_KV   65920
#define AE_TL   9216
#define AE_KVST 18432
#define AE_P    102784
#define AE_PTL  2304
#define AE_PST  4608
#define AE_QS   102784
#define SMEM_EVEN 112000

__global__ __launch_bounds__(256) void attn_even_k(
    const float* __restrict__ Qh,
    const __nv_bfloat16* __restrict__ Kbhi, const __nv_bfloat16* __restrict__ Kblo,
    const __nv_bfloat16* __restrict__ Vbhi, const __nv_bfloat16* __restrict__ Vblo,
    const float* __restrict__ mask_s,
    float* __restrict__ attn_s,
    __nv_bfloat16* __restrict__ cat_hi, __nv_bfloat16* __restrict__ cat_lo)
{
    extern __shared__ char smem[];
    float* Ssm  = (float*)smem;                 // [16][1028]
    float* Qs   = (float*)(smem + AE_QS);       // [16][68] (aliases P region)
    float* sinv = (float*)(smem + AE_SINV);
    uint32_t sb;
    asm("{ .reg .u64 u; cvta.to.shared.u64 u, %1; cvt.u32.u64 %0, u; }" : "=r"(sb) : "l"(smem));

    const int qt = blockIdx.x, j = blockIdx.y, b = blockIdx.z;
    const int h = 2 * j;
    const int tid = threadIdx.x;
    const int warp = tid >> 5, lane = tid & 31;
    const int g = lane >> 2, t4 = lane & 3;
    const int n0 = warp * 8;                    // 8 warps x 8 cols
    const size_t headoff = (size_t)(b * 16 + h) * 1024 * 64;
    const float* Qb = Qh + headoff;
    const int r0 = qt * 16;

    // cp.async mapping: 64 rows x 8 chunks(16B); 256 threads -> rows krow, krow+32
    const int krow = tid >> 3, kc16 = tid & 7;
    const uint32_t kvd0 = (uint32_t)(krow * 144 + kc16 * 16);
    const uint32_t kvd1 = (uint32_t)((krow + 32) * 144 + kc16 * 16);
    const size_t   ks0 = (headoff + (size_t)krow * 64 + kc16 * 8) * 2;
    const size_t   ks1 = (headoff + (size_t)(krow + 32) * 64 + kc16 * 8) * 2;

    auto prefT = [&](const __nv_bfloat16* Hhi, const __nv_bfloat16* Hlo, int kt, int slot) {
        uint32_t d = sb + AE_KV + (uint32_t)slot * AE_KVST;
        size_t off = (size_t)kt * 64 * 64 * 2;
        CP_ASYNC16(d + kvd0,          (const char*)Hhi + ks0 + off);
        CP_ASYNC16(d + kvd0 + AE_TL,  (const char*)Hlo + ks0 + off);
        CP_ASYNC16(d + kvd1,          (const char*)Hhi + ks1 + off);
        CP_ASYNC16(d + kvd1 + AE_TL,  (const char*)Hlo + ks1 + off);
    };

    const int pr = tid >> 4, pc = (tid & 15) * 4;   // P convert: 16 x 64

    prefT(Kbhi, Kblo, 0, 0); CP_COMMIT();
    prefT(Kbhi, Kblo, 1, 1); CP_COMMIT();
    {
        int r = tid >> 4, c = (tid & 15) * 4;       // 16 rows x 16 f4 = 256 thr
        float4 v = *(const float4*)(Qb + (size_t)(r0 + r) * 64 + c);
        *(float4*)&Qs[r * 68 + c] = v;
    }
    __syncthreads();

    // Q A-fragments (m0 = 0: rows g, g+8)
    uint32_t qhF[4][4], qlF[4][4];
    #pragma unroll
    for (int ks = 0; ks < 4; ks++) {
        int kc = ks * 16 + 2 * t4;
        split_pack(Qs[g*68 + kc],       Qs[g*68 + kc + 1],       qhF[ks][0], qlF[ks][0]);
        split_pack(Qs[(g+8)*68 + kc],   Qs[(g+8)*68 + kc + 1],   qhF[ks][1], qlF[ks][1]);
        split_pack(Qs[g*68 + kc + 8],   Qs[g*68 + kc + 9],       qhF[ks][2], qlF[ks][2]);
        split_pack(Qs[(g+8)*68 + kc+8], Qs[(g+8)*68 + kc + 9],   qhF[ks][3], qlF[ks][3]);
    }
    __syncthreads();   // Q frags done before P region (alias) is written in PV

    const int lrow = (lane & 7);
    const uint32_t lsel4 = (uint32_t)((lane >> 3) * 16);

    const float* mrow0 = mask_s + (size_t)(r0 + g) * 1024 + n0 + 2 * t4;
    const float* mrow1 = mask_s + (size_t)(r0 + g + 8) * 1024 + n0 + 2 * t4;
    float2 mk0 = *(const float2*)(mrow0);
    float2 mk1 = *(const float2*)(mrow1);

    // ---- S = Q K^T over 16 K tiles (2-slot double buffer) ----
    for (int kt = 0; kt < 16; kt++) {
        const int st = kt & 1;
        if (kt < 15) { CP_WAIT(1); } else { CP_WAIT(0); }
        __syncthreads();

        float2 nk0, nk1;
        if (kt < 15) {
            nk0 = *(const float2*)(mrow0 + (kt + 1) * 64);
            nk1 = *(const float2*)(mrow1 + (kt + 1) * 64);
        }

        float accS[4] = {0.f, 0.f, 0.f, 0.f};
        const uint32_t kb_hi = sb + AE_KV + (uint32_t)st * AE_KVST;
        uint32_t bh[4][2], bl[4][2];
        #pragma unroll
        for (int kp = 0; kp < 2; kp++) {
            uint32_t addr = kb_hi + (uint32_t)(n0 + lrow) * 144 + kp * 64 + lsel4;
            LDSM_X4(bh[2*kp][0], bh[2*kp][1], bh[2*kp+1][0], bh[2*kp+1][1], addr);
            LDSM_X4(bl[2*kp][0], bl[2*kp][1], bl[2*kp+1][0], bl[2*kp+1][1], addr + AE_TL);
        }
        #pragma unroll
        for (int ks = 0; ks < 4; ks++) {
            mma_bf16(accS, qhF[ks], bh[ks]);
            mma_bf16(accS, qhF[ks], bl[ks]);
            mma_bf16(accS, qlF[ks], bh[ks]);
        }
        int cbase = kt * 64 + n0 + 2 * t4;
        *(float2*)&Ssm[g * SSTR + cbase] =
            make_float2(accS[0] * 0.125f + mk0.x, accS[1] * 0.125f + mk0.y);
        *(float2*)&Ssm[(g + 8) * SSTR + cbase] =
            make_float2(accS[2] * 0.125f + mk1.x, accS[3] * 0.125f + mk1.y);
        mk0 = nk0; mk1 = nk1;

        __syncthreads();
        if (kt + 2 < 16) { prefT(Kbhi, Kblo, kt + 2, st); CP_COMMIT(); }
    }

    // Start V pipeline (overlaps softmax)
    prefT(Vbhi, Vblo, 0, 0); CP_COMMIT();
    prefT(Vbhi, Vblo, 1, 1); CP_COMMIT();

    // ---- softmax: 8 warps x 2 rows ----
    for (int rr = warp * 2; rr < warp * 2 + 2; rr++) {
        const int grow = r0 + rr;
        float* Srow = Ssm + rr * SSTR;
        float mx = -1e30f;
        for (int c = lane; c < 1024; c += 32) mx = fmaxf(mx, Srow[c]);
        #pragma unroll
        for (int o = 16; o > 0; o >>= 1) mx = fmaxf(mx, __shfl_xor_sync(0xffffffffu, mx, o));
        float sum = 0.f;
        for (int c = lane; c < 1024; c += 32) {
            float e = __expf(Srow[c] - mx);
            Srow[c] = e;
            sum += e;
        }
        #pragma unroll
        for (int o = 16; o > 0; o >>= 1) sum += __shfl_xor_sync(0xffffffffu, sum, o);
        float inv = 1.f / sum;
        if (lane == 0) sinv[rr] = inv;
        float* arow = attn_s + ((size_t)(b * 8 + j) * 1024 + grow) * 1024;
        for (int c = lane; c < 1024; c += 32)
            __stcs(arow + c, Srow[c] * inv);
    }
    __syncthreads();

    // ---- O = P V over 16 V tiles (R12-style, 2-slot rings) ----
    float accO[4] = {0.f, 0.f, 0.f, 0.f};
    const int sub = lane >> 3, r8 = lane & 7;
    const uint32_t poff = (uint32_t)((r8 + (sub & 1) * 8) * 144 + (sub >> 1) * 16);
    const int vrow = (lane & 15);
    const float pinv = sinv[pr];

    for (int kt = 0; kt < 16; kt++) {
        const int st = kt & 1;
        // convert P slice (16x64) -> bf16 hi/lo, normalized
        {
            float4 pv = *(const float4*)&Ssm[pr * SSTR + kt * 64 + pc];
            pv.x *= pinv; pv.y *= pinv; pv.z *= pinv; pv.w *= pinv;
            uint32_t h0, h1, l0, l1;
            split_pack(pv.x, pv.y, h0, l0);
            split_pack(pv.z, pv.w, h1, l1);
            char* dp = smem + AE_P + st * AE_PST + pr * 144 + pc * 2;
            *(uint2*)dp            = make_uint2(h0, h1);
            *(uint2*)(dp + AE_PTL) = make_uint2(l0, l1);
        }
        if (kt < 15) { CP_WAIT(1); } else { CP_WAIT(0); }
        __syncthreads();

        const uint32_t pb = sb + AE_P + (uint32_t)st * AE_PST;
        const uint32_t vb = sb + AE_KV + (uint32_t)st * AE_KVST;
        #pragma unroll
        for (int ks = 0; ks < 4; ks++) {
            uint32_t ph[4], pl[4];
            LDSM_X4(ph[0], ph[1], ph[2], ph[3], pb + poff + ks * 32);
            LDSM_X4(pl[0], pl[1], pl[2], pl[3], pb + AE_PTL + poff + ks * 32);
            uint32_t vh[2], vl[2];
            uint32_t va = vb + (uint32_t)(ks * 16 + vrow) * 144 + n0 * 2;
            LDSM_X2_T(vh[0], vh[1], va);
            LDSM_X2_T(vl[0], vl[1], va + AE_TL);
            mma_bf16(accO, ph, vh);
            mma_bf16(accO, ph, vl);
            mma_bf16(accO, pl, vh);
        }
        __syncthreads();
        if (kt + 2 < 16) { prefT(Vbhi, Vblo, kt + 2, st); CP_COMMIT(); }
    }

    // ---- emit cat as bf16 hi/lo ----
    {
        int c = j * 64 + n0 + 2 * t4;
        size_t i0 = ((size_t)b * 1024 + r0 + g) * 1024 + c;
        size_t i1 = ((size_t)b * 1024 + r0 + g + 8) * 1024 + c;
        uint32_t h0, l0, h1, l1;
        split_pack(accO[0], accO[1], h0, l0);
        split_pack(accO[2], accO[3], h1, l1);
        *(uint32_t*)(cat_hi + i0) = h0;
        *(uint32_t*)(cat_lo + i0) = l0;
        *(uint32_t*)(cat_hi + i1) = h1;
        *(uint32_t*)(cat_lo + i1) = l1;
    }
}

// ---------------------------------------------------------------------------
// Odd-head "feature" attention (unchanged; cat emitted as bf16 hi/lo).
// ---------------------------------------------------------------------------
#define SMEM_FEAT ((2*64*64 + 64*65) * 4)
__global__ __launch_bounds__(512) void attn_feat_k(
    const float* __restrict__ Qh, const float* __restrict__ Kh,
    const float* __restrict__ Vh, const float* __restrict__ mask_f,
    float* __restrict__ attn_f,
    __nv_bfloat16* __restrict__ cat_hi, __nv_bfloat16* __restrict__ cat_lo)
{
    extern __shared__ float sm[];
    float* Qt  = sm;
    float* Kt  = Qt + 4096;
    float* Asm = Kt + 4096;

    const int jp = blockIdx.x, b = blockIdx.y;
    const int h = 2 * jp + 1;
    const int tid = threadIdx.x;
    const size_t headoff = (size_t)(b * 16 + h) * 1024 * 64;
    const float* Qb = Qh + headoff;
    const float* Kb = Kh + headoff;
    const float* Vb = Vh + headoff;

    const int m  = tid & 63;
    const int g8 = tid >> 6;

    float acc[8];
    #pragma unroll
    for (int i = 0; i < 8; i++) acc[i] = 0.f;

    for (int lt = 0; lt < 16; lt++) {
        __syncthreads();
        for (int i = tid; i < 1024; i += 512) {
            ((float4*)Qt)[i] = ((const float4*)(Qb + (size_t)lt * 4096))[i];
            ((float4*)Kt)[i] = ((const float4*)(Kb + (size_t)lt * 4096))[i];
        }
        __syncthreads();
        for (int ll = 0; ll < 64; ll++) {
            float kk = Kt[ll * 64 + m];
            #pragma unroll
            for (int i = 0; i < 8; i++)
                acc[i] = fmaf(Qt[ll * 64 + g8 + 8 * i], kk, acc[i]);
        }
    }
    __syncthreads();
    #pragma unroll
    for (int i = 0; i < 8; i++) {
        int n = g8 + 8 * i;
        Asm[n * 65 + m] = acc[i] * 0.125f + mask_f[n * 64 + m];
    }
    __syncthreads();

    const int warp = tid >> 5, lane = tid & 31;
    for (int n = warp * 4; n < warp * 4 + 4; n++) {
        float* row = Asm + n * 65;
        float a0 = row[lane], a1 = row[lane + 32];
        float mx = fmaxf(a0, a1);
        #pragma unroll
        for (int o = 16; o > 0; o >>= 1) mx = fmaxf(mx, __shfl_xor_sync(0xffffffffu, mx, o));
        float e0 = __expf(a0 - mx), e1 = __expf(a1 - mx);
        float s = e0 + e1;
        #pragma unroll
        for (int o = 16; o > 0; o >>= 1) s += __shfl_xor_sync(0xffffffffu, s, o);
        float inv = 1.f / s;
        e0 *= inv; e1 *= inv;
        row[lane] = e0; row[lane + 32] = e1;
        float* grow = attn_f + ((size_t)(b * 8 + jp) * 64 + n) * 64;
        grow[lane] = e0; grow[lane + 32] = e1;
    }
    __syncthreads();

    float* Vt = Qt;
    const int n2 = m;
    for (int lt = 0; lt < 16; lt++) {
        __syncthreads();
        for (int i = tid; i < 1024; i += 512)
            ((float4*)Vt)[i] = ((const float4*)(Vb + (size_t)lt * 4096))[i];
        __syncthreads();

        float accO[8];
        #pragma unroll
        for (int i = 0; i < 8; i++) accO[i] = 0.f;
        for (int mm = 0; mm < 64; mm++) {
            float aa = Asm[n2 * 65 + mm];
            #pragma unroll
            for (int i = 0; i < 8; i++)
                accO[i] = fmaf(Vt[(g8 + 8 * i) * 64 + mm], aa, accO[i]);
        }
        #pragma unroll
        for (int i = 0; i < 8; i++) {
            int ll = g8 + 8 * i;
            size_t idx = ((size_t)b * 1024 + lt * 64 + ll) * 1024 + (8 + jp) * 64 + n2;
            float x = accO[i];
            __nv_bfloat16 hb = __float2bfloat16(x);
            __nv_bfloat16 lb = __float2bfloat16(x - __bfloat162float(hb));
            cat_hi[idx] = hb;
            cat_lo[idx] = lb;
        }
    }
}

// ---------------------------------------------------------------------------
extern "C" void kernel_launch(void* const* d_in, const int* in_sizes, int n_in,
                              void* d_out, int out_size)
{
    const float* q      = (const float*)d_in[0];
    const float* k      = (const float*)d_in[1];
    const float* v      = (const float*)d_in[2];
    const float* mask_s = (const float*)d_in[3];
    const float* mask_f = (const float*)d_in[4];
    const float* Wq     = (const float*)d_in[5];
    const float* Wk     = (const float*)d_in[6];
    const float* Wv     = (const float*)d_in[7];
    const float* Wo     = (const float*)d_in[8];

    float* out    = (float*)d_out;
    float* attn_s = out + OUT_ELEMS;
    float* attn_f = attn_s + ATTNS_ELEMS;

    float *qh, *kh, *vh;
    __nv_bfloat16 *ahi, *alo, *whi, *wlo, *kbhi, *kblo, *vbhi, *vblo;
    cudaGetSymbolAddress((void**)&qh,  g_qh);
    cudaGetSymbolAddress((void**)&kh,  g_kh);
    cudaGetSymbolAddress((void**)&vh,  g_vh);
    cudaGetSymbolAddress((void**)&ahi, g_ahi3);
    cudaGetSymbolAddress((void**)&alo, g_alo3);
    cudaGetSymbolAddress((void**)&whi, g_whi4);
    cudaGetSymbolAddress((void**)&wlo, g_wlo4);
    cudaGetSymbolAddress((void**)&kbhi, g_kbhi);
    cudaGetSymbolAddress((void**)&kblo, g_kblo);
    cudaGetSymbolAddress((void**)&vbhi, g_vbhi);
    cudaGetSymbolAddress((void**)&vblo, g_vblo);

    cudaFuncSetAttribute(attn_even_k, cudaFuncAttributeMaxDynamicSharedMemorySize, SMEM_EVEN);
    cudaFuncSetAttribute(attn_feat_k, cudaFuncAttributeMaxDynamicSharedMemorySize, SMEM_FEAT);
    cudaFuncSetAttribute(gemm_qkv_k, cudaFuncAttributeMaxDynamicSharedMemorySize, GSMEM);
    cudaFuncSetAttribute(gemm_out_k, cudaFuncAttributeMaxDynamicSharedMemorySize, GSMEM);

    dim3 ggrid3(DIMn / 128, (Bn * Ln) / 128, 3);
    dim3 ggrid(DIMn / 128, (Bn * Ln) / 128);
    dim3 sgrid3(OUT_ELEMS / (256 * 4), 3);
    dim3 wgrid4(32, 32, 4), wblk(32, 8);

    const size_t WO = (size_t)DIMn * DIMn;

    split_a3_k<<<sgrid3, 256>>>(q, k, v, ahi, alo);
    split_w4_k<<<wgrid4, wblk>>>(Wq, Wk, Wv, Wo, whi, wlo);

    gemm_qkv_k<<<ggrid3, 256, GSMEM>>>(ahi, alo, whi, wlo, qh, kh, vh,
                                       kbhi, kblo, vbhi, vblo);

    attn_even_k<<<dim3(64, 8, 16), 256, SMEM_EVEN>>>(qh, kbhi, kblo, vbhi, vblo,
                                                     mask_s, attn_s, ahi, alo);
    attn_feat_k<<<dim3(8, 16), 512, SMEM_FEAT>>>(qh, kh, vh, mask_f, attn_f, ahi, alo);

    gemm_out_k<<<ggrid, 256, GSMEM>>>(ahi, alo, whi + 3 * WO, wlo + 3 * WO, out);
}

// round 17
// speedup vs baseline: 1.1664x; 1.0520x over previous
#include <cuda_runtime.h>
#include <cuda_bf16.h>
#include <cstdint>
#include <cstddef>

// Problem constants
#define Bn   16
#define Ln   1024
#define DIMn 1024
#define NH   16
#define DK   64

#define OUT_ELEMS    (16*1024*1024)
#define ATTNS_ELEMS  (16*8*1024*1024)
#define ATTNF_ELEMS  (16*8*64*64)

// fp32 scratch (head-major Qh/Kh/Vh)
__device__ float g_qh[OUT_ELEMS];
__device__ float g_kh[OUT_ELEMS];
__device__ float g_vh[OUT_ELEMS];
// bf16 split scratch: 3 activation tensors + 4 weights
__device__ __nv_bfloat16 g_ahi3[3*OUT_ELEMS];
__device__ __nv_bfloat16 g_alo3[3*OUT_ELEMS];
__device__ __nv_bfloat16 g_whi4[4*DIMn*DIMn];
__device__ __nv_bfloat16 g_wlo4[4*DIMn*DIMn];
// bf16 head-major K/V echoed by the QKV GEMM epilogue
__device__ __nv_bfloat16 g_kbhi[OUT_ELEMS];
__device__ __nv_bfloat16 g_kblo[OUT_ELEMS];
__device__ __nv_bfloat16 g_vbhi[OUT_ELEMS];
__device__ __nv_bfloat16 g_vblo[OUT_ELEMS];

// ===========================================================================
// Common helpers
// ===========================================================================
#define CP_ASYNC16(dst, src) \
    asm volatile("cp.async.cg.shared.global [%0], [%1], 16;\n" :: "r"(dst), "l"(src))
#define CP_COMMIT() asm volatile("cp.async.commit_group;\n" ::: "memory")
#define CP_WAIT(n)  asm volatile("cp.async.wait_group %0;\n" :: "n"(n) : "memory")

#define LDSM_X4(r0, r1, r2, r3, addr) \
    asm volatile("ldmatrix.sync.aligned.m8n8.x4.shared.b16 {%0,%1,%2,%3}, [%4];" \
                 : "=r"(r0), "=r"(r1), "=r"(r2), "=r"(r3) : "r"(addr))
#define LDSM_X2_T(r0, r1, addr) \
    asm volatile("ldmatrix.sync.aligned.m8n8.x2.trans.shared.b16 {%0,%1}, [%2];" \
                 : "=r"(r0), "=r"(r1) : "r"(addr))

__device__ __forceinline__ void mma_bf16(float c[4], const uint32_t a[4], const uint32_t b[2]) {
    asm volatile(
        "mma.sync.aligned.m16n8k16.row.col.f32.bf16.bf16.f32 "
        "{%0,%1,%2,%3}, {%4,%5,%6,%7}, {%8,%9}, {%0,%1,%2,%3};\n"
        : "+f"(c[0]), "+f"(c[1]), "+f"(c[2]), "+f"(c[3])
        : "r"(a[0]), "r"(a[1]), "r"(a[2]), "r"(a[3]), "r"(b[0]), "r"(b[1]));
}

static __device__ __forceinline__ void split_pack(float x0, float x1,
                                                  uint32_t& hi, uint32_t& lo) {
    __nv_bfloat16 h0 = __float2bfloat16(x0);
    __nv_bfloat16 h1 = __float2bfloat16(x1);
    __nv_bfloat16 l0 = __float2bfloat16(x0 - __bfloat162float(h0));
    __nv_bfloat16 l1 = __float2bfloat16(x1 - __bfloat162float(h1));
    __nv_bfloat162 hp(h0, h1), lp(l0, l1);
    hi = *reinterpret_cast<uint32_t*>(&hp);
    lo = *reinterpret_cast<uint32_t*>(&lp);
}

// ===========================================================================
// Split kernels (fp32 -> bf16 hi/lo)
// ===========================================================================
__global__ __launch_bounds__(256) void split_a3_k(
    const float* __restrict__ X0, const float* __restrict__ X1,
    const float* __restrict__ X2,
    __nv_bfloat16* __restrict__ hi, __nv_bfloat16* __restrict__ lo)
{
    const int t = blockIdx.y;
    const float* X = (t == 0) ? X0 : (t == 1) ? X1 : X2;
    size_t obase = (size_t)t * OUT_ELEMS;
    int i = (blockIdx.x * 256 + threadIdx.x) * 4;
    float4 v = *(const float4*)(X + i);
    float x[4] = {v.x, v.y, v.z, v.w};
    __nv_bfloat16 h[4], l[4];
    #pragma unroll
    for (int j = 0; j < 4; j++) {
        h[j] = __float2bfloat16(x[j]);
        l[j] = __float2bfloat16(x[j] - __bfloat162float(h[j]));
    }
    __nv_bfloat162* hp = (__nv_bfloat162*)(hi + obase + i);
    __nv_bfloat162* lp = (__nv_bfloat162*)(lo + obase + i);
    hp[0] = __nv_bfloat162{h[0], h[1]}; hp[1] = __nv_bfloat162{h[2], h[3]};
    lp[0] = __nv_bfloat162{l[0], l[1]}; lp[1] = __nv_bfloat162{l[2], l[3]};
}

__global__ __launch_bounds__(256) void split_w4_k(
    const float* __restrict__ W0, const float* __restrict__ W1,
    const float* __restrict__ W2, const float* __restrict__ W3,
    __nv_bfloat16* __restrict__ hi, __nv_bfloat16* __restrict__ lo)
{
    __shared__ float t[32][33];
    const int wz = blockIdx.z;
    const float* W = (wz == 0) ? W0 : (wz == 1) ? W1 : (wz == 2) ? W2 : W3;
    size_t obase = (size_t)wz * DIMn * DIMn;
    const int tx = threadIdx.x, ty = threadIdx.y;
    const int n0 = blockIdx.x * 32, k0 = blockIdx.y * 32;
    #pragma unroll
    for (int j = 0; j < 32; j += 8)
        t[ty + j][tx] = W[(size_t)(k0 + ty + j) * DIMn + n0 + tx];
    __syncthreads();
    #pragma unroll
    for (int j = 0; j < 32; j += 8) {
        int n = n0 + ty + j, kk = k0 + tx;
        float x = t[tx][ty + j];
        __nv_bfloat16 h = __float2bfloat16(x);
        __nv_bfloat16 l = __float2bfloat16(x - __bfloat162float(h));
        hi[obase + (size_t)n * DIMn + kk] = h;
        lo[obase + (size_t)n * DIMn + kk] = l;
    }
}

// ===========================================================================
// Split-bf16 mma.sync GEMM mainloop (PASSING, unchanged).
// ===========================================================================
#define RS      40
#define TILB    (128*RS*2)
#define STAGEB  (4*TILB)
#define GSMEM   (2*STAGEB)

template<int MODE>
__device__ __forceinline__ void gemm_body(
    const __nv_bfloat16* __restrict__ Ahi, const __nv_bfloat16* __restrict__ Alo,
    const __nv_bfloat16* __restrict__ Bhi, const __nv_bfloat16* __restrict__ Blo,
    float* __restrict__ C, __nv_bfloat16* __restrict__ Ehi,
    __nv_bfloat16* __restrict__ Elo, char* smem)
{
    uint32_t sb;
    asm("{ .reg .u64 u; cvta.to.shared.u64 u, %1; cvt.u32.u64 %0, u; }" : "=r"(sb) : "l"(smem));

    const int tid  = threadIdx.x;
    const int lane = tid & 31;
    const int warp = tid >> 5;
    const int wm   = warp >> 2;
    const int wn   = warp & 3;
    const int g    = lane >> 2;
    const int t4   = lane & 3;

    const int row0 = blockIdx.y * 128;
    const int col0 = blockIdx.x * 128;

    const int sub = lane >> 3, r8 = lane & 7;
    const uint32_t loffA = (uint32_t)((r8 + (sub & 1) * 8) * 80 + (sub >> 1) * 16);
    const uint32_t loffB = (uint32_t)((r8 + (sub >> 1) * 8) * 80 + (sub & 1) * 16);

    const int ra = tid >> 2, ca = tid & 3;
    const int rb = (tid + 256) >> 2, cb = ca;

    auto prefetch = [&](int c, int st) {
        const int kc = c * 32;
        uint32_t s0 = sb + (uint32_t)st * STAGEB;
        {
            uint32_t d = s0 + (uint32_t)(ra * 80 + ca * 16);
            size_t ga = ((size_t)(row0 + ra) * 1024 + kc + ca * 8) * 2;
            size_t gb = ((size_t)(col0 + ra) * 1024 + kc + ca * 8) * 2;
            CP_ASYNC16(d,            (const char*)Ahi + ga);
            CP_ASYNC16(d + TILB,     (const char*)Alo + ga);
            CP_ASYNC16(d + 2*TILB,   (const char*)Bhi + gb);
            CP_ASYNC16(d + 3*TILB,   (const char*)Blo + gb);
        }
        {
            uint32_t d = s0 + (uint32_t)(rb * 80 + cb * 16);
            size_t ga = ((size_t)(row0 + rb) * 1024 + kc + cb * 8) * 2;
            size_t gb = ((size_t)(col0 + rb) * 1024 + kc + cb * 8) * 2;
            CP_ASYNC16(d,            (const char*)Ahi + ga);
            CP_ASYNC16(d + TILB,     (const char*)Alo + ga);
            CP_ASYNC16(d + 2*TILB,   (const char*)Bhi + gb);
            CP_ASYNC16(d + 3*TILB,   (const char*)Blo + gb);
        }
    };

    float acc[4][4][4];
    #pragma unroll
    for (int mt = 0; mt < 4; mt++)
        #pragma unroll
        for (int nt = 0; nt < 4; nt++)
            #pragma unroll
            for (int i = 0; i < 4; i++) acc[mt][nt][i] = 0.f;

    prefetch(0, 0); CP_COMMIT();
    prefetch(1, 1); CP_COMMIT();

    const int nk = 32;
    for (int c = 0; c < nk; c++) {
        const int st = c & 1;
        if (c + 1 < nk) { CP_WAIT(1); } else { CP_WAIT(0); }
        __syncthreads();

        const uint32_t s0 = sb + (uint32_t)st * STAGEB;
        const uint32_t aB = s0 + (uint32_t)(wm * 64) * 80;
        const uint32_t bB = s0 + 2 * TILB + (uint32_t)(wn * 32) * 80;

        #pragma unroll
        for (int ks = 0; ks < 2; ks++) {
            const uint32_t kb = ks * 32;
            uint32_t bh[4][2], bl[4][2];
            #pragma unroll
            for (int p = 0; p < 2; p++) {
                uint32_t base = bB + (uint32_t)(p * 16) * 80 + kb;
                LDSM_X4(bh[2*p][0], bh[2*p][1], bh[2*p+1][0], bh[2*p+1][1], base + loffB);
                LDSM_X4(bl[2*p][0], bl[2*p][1], bl[2*p+1][0], bl[2*p+1][1], base + TILB + loffB);
            }
            #pragma unroll
            for (int mt = 0; mt < 4; mt++) {
                uint32_t abase = aB + (uint32_t)(mt * 16) * 80 + kb;
                uint32_t ah[4], al[4];
                LDSM_X4(ah[0], ah[1], ah[2], ah[3], abase + loffA);
                LDSM_X4(al[0], al[1], al[2], al[3], abase + TILB + loffA);
                #pragma unroll
                for (int nt = 0; nt < 4; nt++) {
                    mma_bf16(acc[mt][nt], ah, bh[nt]);
                    mma_bf16(acc[mt][nt], ah, bl[nt]);
                    mma_bf16(acc[mt][nt], al, bh[nt]);
                }
            }
        }
        __syncthreads();
        if (c + 2 < nk) { prefetch(c + 2, st); CP_COMMIT(); }
    }

    #pragma unroll
    for (int mt = 0; mt < 4; mt++) {
        #pragma unroll
        for (int nt = 0; nt < 4; nt++) {
            int r = row0 + wm * 64 + mt * 16 + g;
            int c = col0 + wn * 32 + nt * 8 + 2 * t4;
            float2 v0 = make_float2(acc[mt][nt][0], acc[mt][nt][1]);
            float2 v1 = make_float2(acc[mt][nt][2], acc[mt][nt][3]);
            if (MODE == 0) {
                __stcs((float2*)(C + (size_t)r * 1024 + c), v0);
                __stcs((float2*)(C + (size_t)(r + 8) * 1024 + c), v1);
            } else {
                int b_ = r >> 10, lr = r & 1023;
                int h_ = c >> 6,  d_ = c & 63;
                size_t base = ((size_t)(b_ * 16 + h_) * 1024) * 64 + d_;
                size_t i0 = base + (size_t)lr * 64;
                size_t i1 = base + (size_t)(lr + 8) * 64;
                *(float2*)(C + i0) = v0;
                *(float2*)(C + i1) = v1;
                if (Ehi) {
                    uint32_t h0, l0w, h1, l1w;
                    split_pack(v0.x, v0.y, h0, l0w);
                    split_pack(v1.x, v1.y, h1, l1w);
                    *(uint32_t*)(Ehi + i0) = h0;
                    *(uint32_t*)(Elo + i0) = l0w;
                    *(uint32_t*)(Ehi + i1) = h1;
                    *(uint32_t*)(Elo + i1) = l1w;
                }
            }
        }
    }
}

__global__ __launch_bounds__(256, 2) void gemm_qkv_k(
    const __nv_bfloat16* __restrict__ Ahi, const __nv_bfloat16* __restrict__ Alo,
    const __nv_bfloat16* __restrict__ Whi, const __nv_bfloat16* __restrict__ Wlo,
    float* __restrict__ Q, float* __restrict__ K, float* __restrict__ V,
    __nv_bfloat16* __restrict__ kbhi, __nv_bfloat16* __restrict__ kblo,
    __nv_bfloat16* __restrict__ vbhi, __nv_bfloat16* __restrict__ vblo)
{
    extern __shared__ char smem[];
    const int z = blockIdx.z;
    const size_t AO = (size_t)OUT_ELEMS, WO = (size_t)DIMn * DIMn;
    float* C = (z == 0) ? Q : (z == 1) ? K : V;
    __nv_bfloat16* Ehi = (z == 0) ? nullptr : (z == 1) ? kbhi : vbhi;
    __nv_bfloat16* Elo = (z == 0) ? nullptr : (z == 1) ? kblo : vblo;
    gemm_body<1>(Ahi + z * AO, Alo + z * AO, Whi + z * WO, Wlo + z * WO, C, Ehi, Elo, smem);
}

__global__ __launch_bounds__(256, 2) void gemm_out_k(
    const __nv_bfloat16* __restrict__ Ahi, const __nv_bfloat16* __restrict__ Alo,
    const __nv_bfloat16* __restrict__ Whi, const __nv_bfloat16* __restrict__ Wlo,
    float* __restrict__ C)
{
    extern __shared__ char smem[];
    gemm_body<0>(Ahi, Alo, Whi, Wlo, C, nullptr, nullptr, smem);
}

// ===========================================================================
// Even-head attention (R14 v6, best-passing): 512 threads, 32-row Q tile,
// pre-split K/V cp.async, PV as 2 kt-halves x 2 mt x 2 n-tiles/warp.
// ===========================================================================
#define SSTR 1032
#define AE_SINV 132096
#define AE_KV   132224
#define AE_TL   9216
#define AE_KVST 18432
#define AE_P    205952
#define AE_PTL  4608
#define AE_PST  9216
#define AE_QS   205952
#define SMEM_EVEN 224384

__global__ __launch_bounds__(512) void attn_even_k(
    const float* __restrict__ Qh,
    const __nv_bfloat16* __restrict__ Kbhi, const __nv_bfloat16* __restrict__ Kblo,
    const __nv_bfloat16* __restrict__ Vbhi, const __nv_bfloat16* __restrict__ Vblo,
    const float* __restrict__ mask_s,
    float* __restrict__ attn_s,
    __nv_bfloat16* __restrict__ cat_hi, __nv_bfloat16* __restrict__ cat_lo)
{
    extern __shared__ char smem[];
    float* Ssm  = (float*)smem;
    float* Qs   = (float*)(smem + AE_QS);
    float* sinv = (float*)(smem + AE_SINV);
    uint32_t sb;
    asm("{ .reg .u64 u; cvta.to.shared.u64 u, %1; cvt.u32.u64 %0, u; }" : "=r"(sb) : "l"(smem));

    const int qt = blockIdx.x, j = blockIdx.y, b = blockIdx.z;
    const int h = 2 * j;
    const int tid = threadIdx.x;
    const int warp = tid >> 5, lane = tid & 31;
    const int g = lane >> 2, t4 = lane & 3;
    const int mt = warp >> 3, ntw = warp & 7;
    const int m0 = mt * 16, n0 = ntw * 8;
    const size_t headoff = (size_t)(b * 16 + h) * 1024 * 64;
    const float* Qb = Qh + headoff;
    const int r0 = qt * 32;

    const int krow = tid >> 3, kc16 = tid & 7;
    const uint32_t kvdst = (uint32_t)(krow * 144 + kc16 * 16);
    const size_t   kvsrc0 = (headoff + (size_t)krow * 64 + kc16 * 8) * 2;

    auto prefT = [&](const __nv_bfloat16* Hhi, const __nv_bfloat16* Hlo, int kt, int slot) {
        uint32_t d = sb + AE_KV + (uint32_t)slot * AE_KVST + kvdst;
        size_t s = kvsrc0 + (size_t)kt * 64 * 64 * 2;
        CP_ASYNC16(d,         (const char*)Hhi + s);
        CP_ASYNC16(d + AE_TL, (const char*)Hlo + s);
    };

    const int pr = tid >> 4, pc = (tid & 15) * 4;

    prefT(Kbhi, Kblo, 0, 0); CP_COMMIT();
    prefT(Kbhi, Kblo, 1, 1); CP_COMMIT();
    {
        int r = tid >> 4, c = (tid & 15) * 4;
        float4 v = *(const float4*)(Qb + (size_t)(r0 + r) * 64 + c);
        *(float4*)&Qs[r * 68 + c] = v;
    }
    __syncthreads();

    uint32_t qhF[4][4], qlF[4][4];
    #pragma unroll
    for (int ks = 0; ks < 4; ks++) {
        int kc = ks * 16 + 2 * t4;
        split_pack(Qs[(m0+g)*68 + kc],     Qs[(m0+g)*68 + kc + 1],     qhF[ks][0], qlF[ks][0]);
        split_pack(Qs[(m0+g+8)*68 + kc],   Qs[(m0+g+8)*68 + kc + 1],   qhF[ks][1], qlF[ks][1]);
        split_pack(Qs[(m0+g)*68 + kc + 8], Qs[(m0+g)*68 + kc + 9],     qhF[ks][2], qlF[ks][2]);
        split_pack(Qs[(m0+g+8)*68 + kc+8], Qs[(m0+g+8)*68 + kc + 9],   qhF[ks][3], qlF[ks][3]);
    }
    __syncthreads();

    const int lrow = (lane & 7);
    const uint32_t lsel4 = (uint32_t)((lane >> 3) * 16);

    const float* mrow0 = mask_s + (size_t)(r0 + m0 + g) * 1024 + n0 + 2 * t4;
    const float* mrow1 = mask_s + (size_t)(r0 + m0 + g + 8) * 1024 + n0 + 2 * t4;

    float2 mk0 = *(const float2*)(mrow0);
    float2 mk1 = *(const float2*)(mrow1);

    // ---- S = Q K^T over 16 K tiles (3-slot ring) ----
    for (int kt = 0; kt < 16; kt++) {
        const int st = kt % 3;
        if (kt < 15) { CP_WAIT(1); } else { CP_WAIT(0); }
        __syncthreads();

        float2 nk0, nk1;
        if (kt < 15) {
            nk0 = *(const float2*)(mrow0 + (kt + 1) * 64);
            nk1 = *(const float2*)(mrow1 + (kt + 1) * 64);
        }

        float accS[4] = {0.f, 0.f, 0.f, 0.f};
        const uint32_t kb_hi = sb + AE_KV + (uint32_t)st * AE_KVST;
        uint32_t bh[4][2], bl[4][2];
        #pragma unroll
        for (int kp = 0; kp < 2; kp++) {
            uint32_t addr = kb_hi + (uint32_t)(n0 + lrow) * 144 + kp * 64 + lsel4;
            LDSM_X4(bh[2*kp][0], bh[2*kp][1], bh[2*kp+1][0], bh[2*kp+1][1], addr);
            LDSM_X4(bl[2*kp][0], bl[2*kp][1], bl[2*kp+1][0], bl[2*kp+1][1], addr + AE_TL);
        }
        #pragma unroll
        for (int ks = 0; ks < 4; ks++) {
            mma_bf16(accS, qhF[ks], bh[ks]);
            mma_bf16(accS, qhF[ks], bl[ks]);
            mma_bf16(accS, qlF[ks], bh[ks]);
        }
        int cbase = kt * 64 + n0 + 2 * t4;
        *(float2*)&Ssm[(m0+g)*SSTR + cbase] =
            make_float2(accS[0] * 0.125f + mk0.x, accS[1] * 0.125f + mk0.y);
        *(float2*)&Ssm[(m0+g+8)*SSTR + cbase] =
            make_float2(accS[2] * 0.125f + mk1.x, accS[3] * 0.125f + mk1.y);
        mk0 = nk0; mk1 = nk1;

        if (kt + 2 < 16) { prefT(Kbhi, Kblo, kt + 2, (kt + 2) % 3); CP_COMMIT(); }
    }
    __syncthreads();

    // Start V pipeline: two streams (kt, kt+8), 4-slot ring
    auto vslot = [](int kt) { return (kt < 8) ? (kt & 1) : 2 + (kt & 1); };
    prefT(Vbhi, Vblo, 0, vslot(0));
    prefT(Vbhi, Vblo, 8, vslot(8));
    CP_COMMIT();

    // ---- softmax ----
    for (int rr = warp * 2; rr < warp * 2 + 2; rr++) {
        const int grow = r0 + rr;
        float* Srow = Ssm + rr * SSTR;
        float mx = -1e30f;
        for (int c = lane; c < 1024; c += 32) mx = fmaxf(mx, Srow[c]);
        #pragma unroll
        for (int o = 16; o > 0; o >>= 1) mx = fmaxf(mx, __shfl_xor_sync(0xffffffffu, mx, o));
        float sum = 0.f;
        for (int c = lane; c < 1024; c += 32) {
            float e = __expf(Srow[c] - mx);
            Srow[c] = e;
            sum += e;
        }
        #pragma unroll
        for (int o = 16; o > 0; o >>= 1) sum += __shfl_xor_sync(0xffffffffu, sum, o);
        float inv = 1.f / sum;
        if (lane == 0) sinv[rr] = inv;
        float* arow = attn_s + ((size_t)(b * 8 + j) * 1024 + grow) * 1024;
        for (int c = lane; c < 1024; c += 32)
            __stcs(arow + c, Srow[c] * inv);
    }
    __syncthreads();

    // ---- O = P V: 2 kh x 2 mt2 x 2 n-tiles/warp ----
    const int kh   = warp >> 3;
    const int mt2  = (warp >> 2) & 1;
    const int nn   = warp & 3;
    const int pm0  = mt2 * 16;
    const int pn0  = nn * 16;

    float accO[2][4];
    #pragma unroll
    for (int n = 0; n < 2; n++)
        #pragma unroll
        for (int i = 0; i < 4; i++) accO[n][i] = 0.f;

    const int sub = lane >> 3, r8 = lane & 7;
    const uint32_t poff = (uint32_t)((pm0 + r8 + (sub & 1) * 8) * 144 + (sub >> 1) * 16);
    const int vrow = (lane & 15);
    const float pinv = sinv[pr];

    for (int it = 0; it < 8; it++) {
        {
            float4 a = *(const float4*)&Ssm[pr * SSTR + it * 64 + pc];
            float4 bb = *(const float4*)&Ssm[pr * SSTR + (it + 8) * 64 + pc];
            a.x *= pinv; a.y *= pinv; a.z *= pinv; a.w *= pinv;
            bb.x *= pinv; bb.y *= pinv; bb.z *= pinv; bb.w *= pinv;
            uint32_t h0, h1, l0, l1;
            split_pack(a.x, a.y, h0, l0);
            split_pack(a.z, a.w, h1, l1);
            char* dp = smem + AE_P + pr * 144 + pc * 2;
            *(uint2*)dp            = make_uint2(h0, h1);
            *(uint2*)(dp + AE_PTL) = make_uint2(l0, l1);
            split_pack(bb.x, bb.y, h0, l0);
            split_pack(bb.z, bb.w, h1, l1);
            char* dq = smem + AE_P + AE_PST + pr * 144 + pc * 2;
            *(uint2*)dq            = make_uint2(h0, h1);
            *(uint2*)(dq + AE_PTL) = make_uint2(l0, l1);
        }
        if (it < 7) {
            prefT(Vbhi, Vblo, it + 1, vslot(it + 1));
            prefT(Vbhi, Vblo, it + 9, vslot(it + 9));
            CP_COMMIT();
            CP_WAIT(1);
        } else {
            CP_WAIT(0);
        }
        __syncthreads();

        const int ktw = kh * 8 + it;
        const uint32_t pb = sb + AE_P + (uint32_t)kh * AE_PST;
        const uint32_t vb = sb + AE_KV + (uint32_t)vslot(ktw) * AE_KVST;
        #pragma unroll
        for (int ks = 0; ks < 4; ks++) {
            uint32_t ph[4], pl[4];
            LDSM_X4(ph[0], ph[1], ph[2], ph[3], pb + poff + ks * 32);
            LDSM_X4(pl[0], pl[1], pl[2], pl[3], pb + AE_PTL + poff + ks * 32);
            uint32_t vrbase = vb + (uint32_t)(ks * 16 + vrow) * 144;
            #pragma unroll
            for (int n = 0; n < 2; n++) {
                uint32_t vh[2], vl[2];
                uint32_t va = vrbase + (uint32_t)(pn0 + n * 8) * 2;
                LDSM_X2_T(vh[0], vh[1], va);
                LDSM_X2_T(vl[0], vl[1], va + AE_TL);
                mma_bf16(accO[n], ph, vh);
                mma_bf16(accO[n], ph, vl);
                mma_bf16(accO[n], pl, vh);
            }
        }
        __syncthreads();
    }

    // ---- reduce kt-half partials via smem, store cat bf16 hi/lo ----
    float* red = Ssm;
    if (kh == 1) {
        #pragma unroll
        for (int n = 0; n < 2; n++) {
            int c = pn0 + n * 8 + 2 * t4;
            *(float2*)&red[(pm0 + g) * 72 + c]     = make_float2(accO[n][0], accO[n][1]);
            *(float2*)&red[(pm0 + g + 8) * 72 + c] = make_float2(accO[n][2], accO[n][3]);
        }
    }
    __syncthreads();
    if (kh == 0) {
        #pragma unroll
        for (int n = 0; n < 2; n++) {
            int c = pn0 + n * 8 + 2 * t4;
            float2 p0 = *(const float2*)&red[(pm0 + g) * 72 + c];
            float2 p1 = *(const float2*)&red[(pm0 + g + 8) * 72 + c];
            float o0 = accO[n][0] + p0.x, o1 = accO[n][1] + p0.y;
            float o2 = accO[n][2] + p1.x, o3 = accO[n][3] + p1.y;
            int cc = j * 64 + c;
            size_t i0 = ((size_t)b * 1024 + r0 + pm0 + g) * 1024 + cc;
            size_t i1 = ((size_t)b * 1024 + r0 + pm0 + g + 8) * 1024 + cc;
            uint32_t h0, l0, h1, l1;
            split_pack(o0, o1, h0, l0);
            split_pack(o2, o3, h1, l1);
            *(uint32_t*)(cat_hi + i0) = h0;
            *(uint32_t*)(cat_lo + i0) = l0;
            *(uint32_t*)(cat_hi + i1) = h1;
            *(uint32_t*)(cat_lo + i1) = l1;
        }
    }
}

// ---------------------------------------------------------------------------
// Odd-head "feature" attention (512 threads; cat emitted as bf16 hi/lo).
// ---------------------------------------------------------------------------
#define SMEM_FEAT ((2*64*64 + 64*65) * 4)
__global__ __launch_bounds__(512) void attn_feat_k(
    const float* __restrict__ Qh, const float* __restrict__ Kh,
    const float* __restrict__ Vh, const float* __restrict__ mask_f,
    float* __restrict__ attn_f,
    __nv_bfloat16* __restrict__ cat_hi, __nv_bfloat16* __restrict__ cat_lo)
{
    extern __shared__ float sm[];
    float* Qt  = sm;
    float* Kt  = Qt + 4096;
    float* Asm = Kt + 4096;

    const int jp = blockIdx.x, b = blockIdx.y;
    const int h = 2 * jp + 1;
    const int tid = threadIdx.x;
    const size_t headoff = (size_t)(b * 16 + h) * 1024 * 64;
    const float* Qb = Qh + headoff;
    const float* Kb = Kh + headoff;
    const float* Vb = Vh + headoff;

    const int m  = tid & 63;
    const int g8 = tid >> 6;

    float acc[8];
    #pragma unroll
    for (int i = 0; i < 8; i++) acc[i] = 0.f;

    for (int lt = 0; lt < 16; lt++) {
        __syncthreads();
        for (int i = tid; i < 1024; i += 512) {
            ((float4*)Qt)[i] = ((const float4*)(Qb + (size_t)lt * 4096))[i];
            ((float4*)Kt)[i] = ((const float4*)(Kb + (size_t)lt * 4096))[i];
        }
        __syncthreads();
        for (int ll = 0; ll < 64; ll++) {
            float kk = Kt[ll * 64 + m];
            #pragma unroll
            for (int i = 0; i < 8; i++)
                acc[i] = fmaf(Qt[ll * 64 + g8 + 8 * i], kk, acc[i]);
        }
    }
    __syncthreads();
    #pragma unroll
    for (int i = 0; i < 8; i++) {
        int n = g8 + 8 * i;
        Asm[n * 65 + m] = acc[i] * 0.125f + mask_f[n * 64 + m];
    }
    __syncthreads();

    const int warp = tid >> 5, lane = tid & 31;
    for (int n = warp * 4; n < warp * 4 + 4; n++) {
        float* row = Asm + n * 65;
        float a0 = row[lane], a1 = row[lane + 32];
        float mx = fmaxf(a0, a1);
        #pragma unroll
        for (int o = 16; o > 0; o >>= 1) mx = fmaxf(mx, __shfl_xor_sync(0xffffffffu, mx, o));
        float e0 = __expf(a0 - mx), e1 = __expf(a1 - mx);
        float s = e0 + e1;
        #pragma unroll
        for (int o = 16; o > 0; o >>= 1) s += __shfl_xor_sync(0xffffffffu, s, o);
        float inv = 1.f / s;
        e0 *= inv; e1 *= inv;
        row[lane] = e0; row[lane + 32] = e1;
        float* grow = attn_f + ((size_t)(b * 8 + jp) * 64 + n) * 64;
        grow[lane] = e0; grow[lane + 32] = e1;
    }
    __syncthreads();

    float* Vt = Qt;
    const int n2 = m;
    for (int lt = 0; lt < 16; lt++) {
        __syncthreads();
        for (int i = tid; i < 1024; i += 512)
            ((float4*)Vt)[i] = ((const float4*)(Vb + (size_t)lt * 4096))[i];
        __syncthreads();

        float accO[8];
        #pragma unroll
        for (int i = 0; i < 8; i++) accO[i] = 0.f;
        for (int mm = 0; mm < 64; mm++) {
            float aa = Asm[n2 * 65 + mm];
            #pragma unroll
            for (int i = 0; i < 8; i++)
                accO[i] = fmaf(Vt[(g8 + 8 * i) * 64 + mm], aa, accO[i]);
        }
        #pragma unroll
        for (int i = 0; i < 8; i++) {
            int ll = g8 + 8 * i;
            size_t idx = ((size_t)b * 1024 + lt * 64 + ll) * 1024 + (8 + jp) * 64 + n2;
            float x = accO[i];
            __nv_bfloat16 hb = __float2bfloat16(x);
            __nv_bfloat16 lb = __float2bfloat16(x - __bfloat162float(hb));
            cat_hi[idx] = hb;
            cat_lo[idx] = lb;
        }
    }
}

// ---------------------------------------------------------------------------
extern "C" void kernel_launch(void* const* d_in, const int* in_sizes, int n_in,
                              void* d_out, int out_size)
{
    const float* q      = (const float*)d_in[0];
    const float* k      = (const float*)d_in[1];
    const float* v      = (const float*)d_in[2];
    const float* mask_s = (const float*)d_in[3];
    const float* mask_f = (const float*)d_in[4];
    const float* Wq     = (const float*)d_in[5];
    const float* Wk     = (const float*)d_in[6];
    const float* Wv     = (const float*)d_in[7];
    const float* Wo     = (const float*)d_in[8];

    float* out    = (float*)d_out;
    float* attn_s = out + OUT_ELEMS;
    float* attn_f = attn_s + ATTNS_ELEMS;

    float *qh, *kh, *vh;
    __nv_bfloat16 *ahi, *alo, *whi, *wlo, *kbhi, *kblo, *vbhi, *vblo;
    cudaGetSymbolAddress((void**)&qh,  g_qh);
    cudaGetSymbolAddress((void**)&kh,  g_kh);
    cudaGetSymbolAddress((void**)&vh,  g_vh);
    cudaGetSymbolAddress((void**)&ahi, g_ahi3);
    cudaGetSymbolAddress((void**)&alo, g_alo3);
    cudaGetSymbolAddress((void**)&whi, g_whi4);
    cudaGetSymbolAddress((void**)&wlo, g_wlo4);
    cudaGetSymbolAddress((void**)&kbhi, g_kbhi);
    cudaGetSymbolAddress((void**)&kblo, g_kblo);
    cudaGetSymbolAddress((void**)&vbhi, g_vbhi);
    cudaGetSymbolAddress((void**)&vblo, g_vblo);

    cudaFuncSetAttribute(attn_even_k, cudaFuncAttributeMaxDynamicSharedMemorySize, SMEM_EVEN);
    cudaFuncSetAttribute(attn_feat_k, cudaFuncAttributeMaxDynamicSharedMemorySize, SMEM_FEAT);
    cudaFuncSetAttribute(gemm_qkv_k, cudaFuncAttributeMaxDynamicSharedMemorySize, GSMEM);
    cudaFuncSetAttribute(gemm_out_k, cudaFuncAttributeMaxDynamicSharedMemorySize, GSMEM);

    dim3 ggrid3(DIMn / 128, (Bn * Ln) / 128, 3);
    dim3 ggrid(DIMn / 128, (Bn * Ln) / 128);
    dim3 sgrid3(OUT_ELEMS / (256 * 4), 3);
    dim3 wgrid4(32, 32, 4), wblk(32, 8);

    const size_t WO = (size_t)DIMn * DIMn;

    split_a3_k<<<sgrid3, 256>>>(q, k, v, ahi, alo);
    split_w4_k<<<wgrid4, wblk>>>(Wq, Wk, Wv, Wo, whi, wlo);

    gemm_qkv_k<<<ggrid3, 256, GSMEM>>>(ahi, alo, whi, wlo, qh, kh, vh,
                                       kbhi, kblo, vbhi, vblo);

    attn_even_k<<<dim3(32, 8, 16), 512, SMEM_EVEN>>>(qh, kbhi, kblo, vbhi, vblo,
                                                     mask_s, attn_s, ahi, alo);
    attn_feat_k<<<dim3(8, 16), 512, SMEM_FEAT>>>(qh, kh, vh, mask_f, attn_f, ahi, alo);

    gemm_out_k<<<ggrid, 256, GSMEM>>>(ahi, alo, whi + 3 * WO, wlo + 3 * WO, out);
}